// round 2
// baseline (speedup 1.0000x reference)
#include <cuda_runtime.h>

#define NN 50000
#define DH 128
#define TILE_M 64

// Scratch (allocation-free rule: __device__ globals)
__device__ float g_s[(size_t)NN * DH];     // aggregation buffer
__device__ float g_h[(size_t)NN * DH];     // hidden features
__device__ float g_inv[NN];                // 1/max(degree,1)
__device__ int   g_cnt[NN];

__global__ void k_zero_cnt(int n) {
    int i = blockIdx.x * blockDim.x + threadIdx.x;
    if (i < n) g_cnt[i] = 0;
}

__global__ void k_count(const int* __restrict__ dst, int E) {
    int e = blockIdx.x * blockDim.x + threadIdx.x;
    if (e < E) atomicAdd(&g_cnt[dst[e]], 1);
}

__global__ void k_inv(int n) {
    int i = blockIdx.x * blockDim.x + threadIdx.x;
    if (i < n) g_inv[i] = 1.0f / (float)max(g_cnt[i], 1);
}

__global__ void k_zero_s(int n4) {
    int i = blockIdx.x * blockDim.x + threadIdx.x;
    if (i < n4) ((float4*)g_s)[i] = make_float4(0.f, 0.f, 0.f, 0.f);
}

// One thread per (edge, float4-chunk): 32 chunks per edge (128 floats).
// Consecutive threads cover one edge's 512B row -> fully coalesced gather,
// fully coalesced vector atomics to the destination row.
__global__ void k_scatter(const float* __restrict__ X,
                          const int* __restrict__ src,
                          const int* __restrict__ dst, int E) {
    int idx = blockIdx.x * blockDim.x + threadIdx.x;
    int tot = E * 32;
    if (idx >= tot) return;
    int e = idx >> 5;
    int q = idx & 31;
    int s = src[e];
    int d = dst[e];
    float4 v = ((const float4*)X)[s * 32 + q];
#if __CUDA_ARCH__ >= 900
    atomicAdd(((float4*)g_s) + d * 32 + q, v);
#else
    float* p = g_s + (size_t)d * DH + q * 4;
    atomicAdd(p + 0, v.x); atomicAdd(p + 1, v.y);
    atomicAdd(p + 2, v.z); atomicAdd(p + 3, v.w);
#endif
}

// Fused GEMM: out = [s*inv | X] @ [wl | wr]^T + bl   (K = 256)
// + optional relu/dropout epilogue.
// Block: 256 threads, TILE_M=64 rows x OUT cols.
// smem: As[64][256] (concat rows), Wt[256][OUT+4] (transposed, padded).
template <int OUT, bool DROP>
__global__ void k_gemm(const float* __restrict__ X,
                       const float* __restrict__ wl,
                       const float* __restrict__ wr,
                       const float* __restrict__ bl,
                       const float* __restrict__ u,
                       float* __restrict__ out, int nrows) {
    constexpr int TPR = OUT / 4;                 // threads per row-group (cols)
    constexpr int RPT = TILE_M * TPR / 256;      // rows per thread
    constexpr int WST = OUT + 4;                 // padded Wt stride (floats)
    extern __shared__ float sm[];
    float* As = sm;                              // TILE_M * 256
    float* Wt = sm + TILE_M * 256;               // 256 * WST

    const int tid = threadIdx.x;
    const int base = blockIdx.x * TILE_M;

    // Stage weights transposed: Wt[k][o] = wl[o][k], Wt[128+k][o] = wr[o][k]
    for (int i = tid; i < 128 * OUT; i += 256) {
        int o = i >> 7;
        int k = i & 127;
        Wt[k * WST + o]         = wl[i];
        Wt[(k + 128) * WST + o] = wr[i];
    }

    // Stage A tile: first 128 k = mean (= s*inv), next 128 k = X row
    const int nr = min(TILE_M, nrows - base);
    for (int i = tid; i < TILE_M * 64; i += 256) {
        int r  = i >> 6;
        int k4 = i & 63;
        float4 v = make_float4(0.f, 0.f, 0.f, 0.f);
        if (r < nr) {
            int row = base + r;
            if (k4 < 32) {
                v = ((const float4*)g_s)[row * 32 + k4];
                float iv = g_inv[row];
                v.x *= iv; v.y *= iv; v.z *= iv; v.w *= iv;
            } else {
                v = ((const float4*)X)[row * 32 + (k4 - 32)];
            }
        }
        ((float4*)As)[i] = v;
    }
    __syncthreads();

    const int rg = tid / TPR;
    const int cg = tid % TPR;                    // cols cg*4 .. cg*4+3
    float acc[RPT][4];
#pragma unroll
    for (int r = 0; r < RPT; r++) {
        acc[r][0] = acc[r][1] = acc[r][2] = acc[r][3] = 0.f;
    }

    const float4* As4 = ((const float4*)As) + (rg * RPT) * 64;
    for (int k = 0; k < 256; k += 4) {
        float4 a[RPT];
#pragma unroll
        for (int r = 0; r < RPT; r++) a[r] = As4[r * 64 + (k >> 2)];
        float4 w0 = ((const float4*)(Wt + (k + 0) * WST))[cg];
        float4 w1 = ((const float4*)(Wt + (k + 1) * WST))[cg];
        float4 w2 = ((const float4*)(Wt + (k + 2) * WST))[cg];
        float4 w3 = ((const float4*)(Wt + (k + 3) * WST))[cg];
#pragma unroll
        for (int r = 0; r < RPT; r++) {
            acc[r][0] += a[r].x * w0.x + a[r].y * w1.x + a[r].z * w2.x + a[r].w * w3.x;
            acc[r][1] += a[r].x * w0.y + a[r].y * w1.y + a[r].z * w2.y + a[r].w * w3.y;
            acc[r][2] += a[r].x * w0.z + a[r].y * w1.z + a[r].z * w2.z + a[r].w * w3.z;
            acc[r][3] += a[r].x * w0.w + a[r].y * w1.w + a[r].z * w2.w + a[r].w * w3.w;
        }
    }

    float4 b4 = ((const float4*)bl)[cg];
#pragma unroll
    for (int r = 0; r < RPT; r++) {
        int lr = rg * RPT + r;
        if (lr < nr) {
            int row = base + lr;
            float4 v;
            v.x = acc[r][0] + b4.x;
            v.y = acc[r][1] + b4.y;
            v.z = acc[r][2] + b4.z;
            v.w = acc[r][3] + b4.w;
            if (DROP) {
                const float kinv = 1.0f / 0.7f;
                float4 uu = ((const float4*)u)[row * 32 + cg];
                v.x = (v.x > 0.f ? v.x : 0.f) * (uu.x >= 0.3f ? kinv : 0.f);
                v.y = (v.y > 0.f ? v.y : 0.f) * (uu.y >= 0.3f ? kinv : 0.f);
                v.z = (v.z > 0.f ? v.z : 0.f) * (uu.z >= 0.3f ? kinv : 0.f);
                v.w = (v.w > 0.f ? v.w : 0.f) * (uu.w >= 0.3f ? kinv : 0.f);
            }
            ((float4*)out)[row * (OUT / 4) + cg] = v;
        }
    }
}

extern "C" void kernel_launch(void* const* d_in, const int* in_sizes, int n_in,
                              void* d_out, int out_size) {
    const float* x   = (const float*)d_in[0];
    const float* u1  = (const float*)d_in[1];
    const float* u2  = (const float*)d_in[2];
    const float* wl0 = (const float*)d_in[3];
    const float* bl0 = (const float*)d_in[4];
    const float* wr0 = (const float*)d_in[5];
    const float* wl1 = (const float*)d_in[6];
    const float* bl1 = (const float*)d_in[7];
    const float* wr1 = (const float*)d_in[8];
    const float* wl2 = (const float*)d_in[9];
    const float* bl2 = (const float*)d_in[10];
    const float* wr2 = (const float*)d_in[11];
    const int*   ei  = (const int*)d_in[12];

    const int N = in_sizes[0] / DH;
    const int E = in_sizes[12] / 2;
    const int* src = ei;
    const int* dst = ei + E;
    float* out = (float*)d_out;

    float* hbuf = nullptr;
    cudaGetSymbolAddress((void**)&hbuf, g_h);

    const size_t smem128 = (size_t)TILE_M * 256 * 4 + 256 * (128 + 4) * 4;
    const size_t smem64  = (size_t)TILE_M * 256 * 4 + 256 * (64 + 4) * 4;
    cudaFuncSetAttribute(k_gemm<128, true>,
                         cudaFuncAttributeMaxDynamicSharedMemorySize, (int)smem128);
    cudaFuncSetAttribute(k_gemm<64, false>,
                         cudaFuncAttributeMaxDynamicSharedMemorySize, (int)smem64);

    const int tb = 256;
    const int n4 = N * DH / 4;
    const int zb = (n4 + tb - 1) / tb;
    const int sb = (E * 32 + tb - 1) / tb;
    const int gb = (N + TILE_M - 1) / TILE_M;

    // Degree (once, reused by all layers)
    k_zero_cnt<<<(N + tb - 1) / tb, tb>>>(N);
    k_count<<<(E + tb - 1) / tb, tb>>>(dst, E);
    k_inv<<<(N + tb - 1) / tb, tb>>>(N);

    // Layer 0: x -> g_h (relu + dropout u1)
    k_zero_s<<<zb, tb>>>(n4);
    k_scatter<<<sb, tb>>>(x, src, dst, E);
    k_gemm<128, true><<<gb, 256, smem128>>>(x, wl0, wr0, bl0, u1, hbuf, N);

    // Layer 1: g_h -> g_h (relu + dropout u2) — in-place is safe: each block
    // reads only its own rows (prologue) before writing them (epilogue).
    k_zero_s<<<zb, tb>>>(n4);
    k_scatter<<<sb, tb>>>(hbuf, src, dst, E);
    k_gemm<128, true><<<gb, 256, smem128>>>(hbuf, wl1, wr1, bl1, u2, hbuf, N);

    // Layer 2: g_h -> d_out (no activation)
    k_zero_s<<<zb, tb>>>(n4);
    k_scatter<<<sb, tb>>>(hbuf, src, dst, E);
    k_gemm<64, false><<<gb, 256, smem64>>>(hbuf, wl2, wr2, bl2, nullptr, out, N);
}

// round 3
// speedup vs baseline: 1.5446x; 1.5446x over previous
#include <cuda_runtime.h>

#define NN 50000
#define EE 800000
#define DH 128

// Scratch (allocation-free rule: __device__ globals)
__device__ float g_s[(size_t)NN * DH];     // mean-aggregated features
__device__ float g_h[(size_t)NN * DH];     // hidden features
__device__ float g_inv[NN];                // 1/max(deg,1)
__device__ int   g_cnt[NN];
__device__ int   g_off[NN + 1];            // CSR row offsets (by dst)
__device__ int   g_cur[NN];                // fill cursors
__device__ int   g_csr[EE];                // src node per CSR slot
__device__ float g_wt0[256 * 128];         // pretransposed [wl|wr]^T, k-major
__device__ float g_wt1[256 * 128];
__device__ float g_wt2[256 * 64];

__global__ void k_zero_cnt(int n) {
    int i = blockIdx.x * blockDim.x + threadIdx.x;
    if (i < n) g_cnt[i] = 0;
}

__global__ void k_count(const int* __restrict__ dst, int E) {
    int e = blockIdx.x * blockDim.x + threadIdx.x;
    if (e < E) atomicAdd(&g_cnt[dst[e]], 1);
}

// Single-block exclusive scan of g_cnt -> g_off, g_cur; also g_inv.
__global__ void k_scan(int n) {
    __shared__ int part[1024];
    int t = threadIdx.x;
    int chunk = (n + 1023) >> 10;
    int lo = t * chunk, hi = min(lo + chunk, n);
    int s = 0;
    for (int i = lo; i < hi; i++) s += g_cnt[i];
    part[t] = s;
    __syncthreads();
    for (int d = 1; d < 1024; d <<= 1) {
        int v = (t >= d) ? part[t - d] : 0;
        __syncthreads();
        part[t] += v;
        __syncthreads();
    }
    int run = (t == 0) ? 0 : part[t - 1];
    for (int i = lo; i < hi; i++) {
        int c = g_cnt[i];
        g_off[i] = run;
        g_cur[i] = run;
        g_inv[i] = 1.0f / (float)max(c, 1);
        run += c;
    }
    if (t == 1023) g_off[n] = run;
}

__global__ void k_fill(const int* __restrict__ src, const int* __restrict__ dst, int E) {
    int e = blockIdx.x * blockDim.x + threadIdx.x;
    if (e < E) {
        int p = atomicAdd(&g_cur[dst[e]], 1);
        g_csr[p] = src[e];
    }
}

// Pretranspose weights: dw[k][n] = (k<128 ? wl[n][k] : wr[n][k-128])
__global__ void k_wt(const float* __restrict__ wl, const float* __restrict__ wr,
                     float* __restrict__ dw, int OUT) {
    int i = blockIdx.x * blockDim.x + threadIdx.x;
    if (i >= 256 * OUT) return;
    int k = i / OUT, n = i - k * OUT;
    dw[i] = (k < 128) ? wl[n * 128 + k] : wr[n * 128 + (k - 128)];
}

// Warp-per-node CSR gather + mean. No atomics, no zero pass.
__global__ void k_gather(const float* __restrict__ X, int n) {
    int w = (blockIdx.x * blockDim.x + threadIdx.x) >> 5;
    int lane = threadIdx.x & 31;
    if (w >= n) return;
    int j0 = g_off[w], j1 = g_off[w + 1];
    const float4* X4 = (const float4*)X;
    float4 a = make_float4(0.f, 0.f, 0.f, 0.f);
    for (int j = j0; j < j1; j++) {
        int s = g_csr[j];
        float4 v = X4[(size_t)s * 32 + lane];
        a.x += v.x; a.y += v.y; a.z += v.z; a.w += v.w;
    }
    float iv = g_inv[w];
    a.x *= iv; a.y *= iv; a.z *= iv; a.w *= iv;
    ((float4*)g_s)[(size_t)w * 32 + lane] = a;
}

// ---------------- FFMA2 (packed f32x2) GEMM ----------------

__device__ __forceinline__ unsigned long long dup2(float v) {
    unsigned long long r;
    asm("mov.b64 %0, {%1, %1};" : "=l"(r) : "f"(v));
    return r;
}
__device__ __forceinline__ void ffma2(unsigned long long& d,
                                      unsigned long long a, unsigned long long b) {
    asm("fma.rn.f32x2 %0, %1, %2, %0;" : "+l"(d) : "l"(a), "l"(b));
}
__device__ __forceinline__ void unpk(unsigned long long p, float& lo, float& hi) {
    asm("mov.b64 {%0, %1}, %2;" : "=f"(lo), "=f"(hi) : "l"(p));
}

// out[128 x OUT] tile = [mean | X](128 x 256) @ Wt(256 x OUT) + b, + relu/dropout.
// 256 threads: tx=tid&31 (cols tx+32c), ty=tid>>5 (rows ty*16..+15 as 8 f32x2 pairs).
// As staged k-major [32][128]: one LDS.128 = 2 packed row-pairs, zero dup MOVs on A.
template<int OUT, bool DROP>
__global__ __launch_bounds__(256, 2)
void k_gemm(const float* __restrict__ Xin, const float* __restrict__ Wt,
            const float* __restrict__ bl, const float* __restrict__ u,
            float* __restrict__ out, int nrows) {
    constexpr int CPT = OUT / 32;       // cols per thread
    constexpr int WV  = OUT / 32;       // W float4s per thread per chunk
    __shared__ __align__(16) float As[32 * 128];
    __shared__ __align__(16) float Ws[32 * OUT];

    const int tid = threadIdx.x;
    const int tx = tid & 31, ty = tid >> 5;
    const int base = blockIdx.x * 128;
    const int nr = min(128, nrows - base);

    const float4* s4 = (const float4*)g_s;
    const float4* x4 = (const float4*)Xin;
    const float4* w4 = (const float4*)Wt;
    const float4 z4 = make_float4(0.f, 0.f, 0.f, 0.f);

    unsigned long long acc[8][CPT];
#pragma unroll
    for (int p = 0; p < 8; p++)
#pragma unroll
        for (int c = 0; c < CPT; c++) acc[p][c] = 0ULL;

    float4 av[4], wv[WV];

    // Prefetch chunk 0 (k 0..31 comes from mean buffer)
#pragma unroll
    for (int t = 0; t < 4; t++) {
        int i = tid + t * 256, m = i >> 3, kq = i & 7;
        av[t] = (m < nr) ? s4[(size_t)(base + m) * 32 + kq] : z4;
    }
#pragma unroll
    for (int t = 0; t < WV; t++) wv[t] = w4[tid + t * 256];

#pragma unroll 1
    for (int c = 0; c < 8; c++) {
        __syncthreads();
        // Stage A transposed (k-major) + W straight
#pragma unroll
        for (int t = 0; t < 4; t++) {
            int i = tid + t * 256, m = i >> 3, kq = i & 7;
            As[(kq * 4 + 0) * 128 + m] = av[t].x;
            As[(kq * 4 + 1) * 128 + m] = av[t].y;
            As[(kq * 4 + 2) * 128 + m] = av[t].z;
            As[(kq * 4 + 3) * 128 + m] = av[t].w;
        }
#pragma unroll
        for (int t = 0; t < WV; t++) ((float4*)Ws)[tid + t * 256] = wv[t];
        __syncthreads();

        // Prefetch next chunk while computing this one
        if (c < 7) {
            int cn = c + 1;
            const float4* src = (cn < 4) ? s4 : x4;
            int kb = (cn & 3) * 8;
#pragma unroll
            for (int t = 0; t < 4; t++) {
                int i = tid + t * 256, m = i >> 3, kq = i & 7;
                av[t] = (m < nr) ? src[(size_t)(base + m) * 32 + kb + kq] : z4;
            }
#pragma unroll
            for (int t = 0; t < WV; t++) wv[t] = w4[cn * 8 * OUT + tid + t * 256];
        }

        // Compute 32 k-steps
#pragma unroll 4
        for (int k = 0; k < 32; k++) {
            const float* ap = &As[k * 128 + ty * 16];
            ulonglong2 a01 = *(const ulonglong2*)(ap + 0);
            ulonglong2 a23 = *(const ulonglong2*)(ap + 4);
            ulonglong2 a45 = *(const ulonglong2*)(ap + 8);
            ulonglong2 a67 = *(const ulonglong2*)(ap + 12);
            unsigned long long a2[8] = {a01.x, a01.y, a23.x, a23.y,
                                        a45.x, a45.y, a67.x, a67.y};
#pragma unroll
            for (int cc = 0; cc < CPT; cc++) {
                unsigned long long w2 = dup2(Ws[k * OUT + tx + 32 * cc]);
#pragma unroll
                for (int p = 0; p < 8; p++) ffma2(acc[p][cc], a2[p], w2);
            }
        }
    }

    // Epilogue: bias + optional relu/dropout; pair p = rows ty*16+2p, +1
    float bv[CPT];
#pragma unroll
    for (int cc = 0; cc < CPT; cc++) bv[cc] = __ldg(&bl[tx + 32 * cc]);
    const float kinv = 1.0f / 0.7f;
#pragma unroll
    for (int p = 0; p < 8; p++) {
        int r0 = ty * 16 + 2 * p;
        if (r0 >= nr) continue;
        int row0 = base + r0;
        bool ok1 = (r0 + 1) < nr;
#pragma unroll
        for (int cc = 0; cc < CPT; cc++) {
            int col = tx + 32 * cc;
            float lo, hi;
            unpk(acc[p][cc], lo, hi);
            lo += bv[cc]; hi += bv[cc];
            if (DROP) {
                float u0 = u[(size_t)row0 * OUT + col];
                lo = (lo > 0.f ? lo : 0.f) * (u0 >= 0.3f ? kinv : 0.f);
            }
            out[(size_t)row0 * OUT + col] = lo;
            if (ok1) {
                if (DROP) {
                    float u1v = u[(size_t)(row0 + 1) * OUT + col];
                    hi = (hi > 0.f ? hi : 0.f) * (u1v >= 0.3f ? kinv : 0.f);
                }
                out[(size_t)(row0 + 1) * OUT + col] = hi;
            }
        }
    }
}

extern "C" void kernel_launch(void* const* d_in, const int* in_sizes, int n_in,
                              void* d_out, int out_size) {
    const float* x   = (const float*)d_in[0];
    const float* u1  = (const float*)d_in[1];
    const float* u2  = (const float*)d_in[2];
    const float* wl0 = (const float*)d_in[3];
    const float* bl0 = (const float*)d_in[4];
    const float* wr0 = (const float*)d_in[5];
    const float* wl1 = (const float*)d_in[6];
    const float* bl1 = (const float*)d_in[7];
    const float* wr1 = (const float*)d_in[8];
    const float* wl2 = (const float*)d_in[9];
    const float* bl2 = (const float*)d_in[10];
    const float* wr2 = (const float*)d_in[11];
    const int*   ei  = (const int*)d_in[12];

    const int N = in_sizes[0] / DH;
    const int E = in_sizes[12] / 2;
    const int* src = ei;
    const int* dst = ei + E;
    float* out = (float*)d_out;

    float *hbuf, *wt0, *wt1, *wt2;
    cudaGetSymbolAddress((void**)&hbuf, g_h);
    cudaGetSymbolAddress((void**)&wt0, g_wt0);
    cudaGetSymbolAddress((void**)&wt1, g_wt1);
    cudaGetSymbolAddress((void**)&wt2, g_wt2);

    const int tb = 256;
    const int gw = (N * 32 + tb - 1) / tb;   // gather: warp per node
    const int gg = (N + 127) / 128;          // gemm: 128-row tiles

    // CSR build (once, reused by all 3 layers)
    k_zero_cnt<<<(N + tb - 1) / tb, tb>>>(N);
    k_count<<<(E + tb - 1) / tb, tb>>>(dst, E);
    k_scan<<<1, 1024>>>(N);
    k_fill<<<(E + tb - 1) / tb, tb>>>(src, dst, E);

    // Weight pretranspose (k-major, [wl|wr] concatenated)
    k_wt<<<(256 * 128 + tb - 1) / tb, tb>>>(wl0, wr0, wt0, 128);
    k_wt<<<(256 * 128 + tb - 1) / tb, tb>>>(wl1, wr1, wt1, 128);
    k_wt<<<(256 * 64 + tb - 1) / tb, tb>>>(wl2, wr2, wt2, 64);

    // Layer 0
    k_gather<<<gw, tb>>>(x, N);
    k_gemm<128, true><<<gg, 256>>>(x, wt0, bl0, u1, hbuf, N);
    // Layer 1 (in-place safe: each block reads only its own rows before writing)
    k_gather<<<gw, tb>>>(hbuf, N);
    k_gemm<128, true><<<gg, 256>>>(hbuf, wt1, bl1, u2, hbuf, N);
    // Layer 2
    k_gather<<<gw, tb>>>(hbuf, N);
    k_gemm<64, false><<<gg, 256>>>(hbuf, wt2, bl2, nullptr, out, N);
}

// round 6
// speedup vs baseline: 1.9558x; 1.2662x over previous
#include <cuda_runtime.h>
#include <cuda_bf16.h>
#include <cstdint>

#define NN 50000
#define EE 800000
#define DH 128
#define NMT 3125           // 50000 / 16 row-tiles

// ---------------- scratch (__device__ globals; no allocs allowed) ----------------
__device__ float g_s[(size_t)NN * DH];     // mean-aggregated features (fp32)
__device__ float g_h[(size_t)NN * DH];     // hidden features (fp32)
__device__ float g_inv[NN];
__device__ int   g_cnt[NN];
__device__ int   g_off[NN + 1];
__device__ int   g_cur[NN];
__device__ int   g_csr[EE];
// A fragment images: [mt][ks(16)][lane(32)][4 x b32]  (bf16x2 packed)
__device__ uint32_t g_ah[(size_t)NMT * 16 * 32 * 4];
__device__ uint32_t g_al[(size_t)NMT * 16 * 32 * 4];
// B fragment images per layer: [ks(16)][nt(<=16)][lane(32)][2 x b32]
__device__ uint32_t g_bh[3][16 * 16 * 32 * 2];
__device__ uint32_t g_bl[3][16 * 16 * 32 * 2];

// ---------------- CSR build ----------------
__global__ void k_zero_cnt(int n) {
    int i = blockIdx.x * blockDim.x + threadIdx.x;
    if (i < n) g_cnt[i] = 0;
}
__global__ void k_count(const int* __restrict__ dst, int E) {
    int e = blockIdx.x * blockDim.x + threadIdx.x;
    if (e < E) atomicAdd(&g_cnt[dst[e]], 1);
}
__global__ void k_scan(int n) {
    __shared__ int part[1024];
    int t = threadIdx.x;
    int chunk = (n + 1023) >> 10;
    int lo = t * chunk, hi = min(lo + chunk, n);
    int s = 0;
    for (int i = lo; i < hi; i++) s += g_cnt[i];
    part[t] = s;
    __syncthreads();
    for (int d = 1; d < 1024; d <<= 1) {
        int v = (t >= d) ? part[t - d] : 0;
        __syncthreads();
        part[t] += v;
        __syncthreads();
    }
    int run = (t == 0) ? 0 : part[t - 1];
    for (int i = lo; i < hi; i++) {
        int c = g_cnt[i];
        g_off[i] = run;
        g_cur[i] = run;
        g_inv[i] = 1.0f / (float)max(c, 1);
        run += c;
    }
    if (t == 1023) g_off[n] = run;
}
__global__ void k_fill(const int* __restrict__ src, const int* __restrict__ dst, int E) {
    int e = blockIdx.x * blockDim.x + threadIdx.x;
    if (e < E) {
        int p = atomicAdd(&g_cur[dst[e]], 1);
        g_csr[p] = src[e];
    }
}

// Warp-per-node CSR gather + mean.
__global__ void k_gather(const float* __restrict__ X, int n) {
    int w = (blockIdx.x * blockDim.x + threadIdx.x) >> 5;
    int lane = threadIdx.x & 31;
    if (w >= n) return;
    int j0 = g_off[w], j1 = g_off[w + 1];
    const float4* X4 = (const float4*)X;
    float4 a = make_float4(0.f, 0.f, 0.f, 0.f);
    for (int j = j0; j < j1; j++) {
        int s = g_csr[j];
        float4 v = X4[(size_t)s * 32 + lane];
        a.x += v.x; a.y += v.y; a.z += v.z; a.w += v.w;
    }
    float iv = g_inv[w];
    a.x *= iv; a.y *= iv; a.z *= iv; a.w *= iv;
    ((float4*)g_s)[(size_t)w * 32 + lane] = a;
}

// ---------------- bf16 helpers ----------------
__device__ __forceinline__ void split2(float a, float b, uint32_t& hi, uint32_t& lo) {
    __nv_bfloat162 h = __floats2bfloat162_rn(a, b);
    hi = *reinterpret_cast<uint32_t*>(&h);
    float ra = a - __bfloat162float(h.x);
    float rb = b - __bfloat162float(h.y);
    __nv_bfloat162 l = __floats2bfloat162_rn(ra, rb);
    lo = *reinterpret_cast<uint32_t*>(&l);
}

// A fragment image builder. idx = (mt*16 + ks)*32 + lane.
// reg r: r0=(row g, k low), r1=(g+8, k low), r2=(g, k+8), r3=(g+8, k+8)
__global__ void k_prep(const float* __restrict__ Xsrc, int nmt, int N) {
    int idx = blockIdx.x * blockDim.x + threadIdx.x;
    if (idx >= nmt * 16 * 32) return;
    int l = idx & 31;
    int mk = idx >> 5;
    int ks = mk & 15;
    int mt = mk >> 4;
    int R0 = mt * 16 + (l >> 2);
    int Kl = 2 * (l & 3) + (ks & 7) * 16;          // col within the 128-col half
    const float* S = (ks < 8) ? g_s : Xsrc;
    uint32_t hi[4], lo[4];
#pragma unroll
    for (int rr = 0; rr < 2; rr++) {
        int row = R0 + 8 * rr;
        bool ok = row < N;
#pragma unroll
        for (int kk = 0; kk < 2; kk++) {
            float2 v = ok ? *(const float2*)(S + (size_t)row * DH + Kl + 8 * kk)
                          : make_float2(0.f, 0.f);
            split2(v.x, v.y, hi[rr + 2 * kk], lo[rr + 2 * kk]);
        }
    }
    ((uint4*)g_ah)[idx] = make_uint4(hi[0], hi[1], hi[2], hi[3]);
    ((uint4*)g_al)[idx] = make_uint4(lo[0], lo[1], lo[2], lo[3]);
}

// B fragment image builder. thread = (ks, nt, lane). reg r: b0=(k low, col n), b1=(k+8, n)
__global__ void k_wtimg(const float* __restrict__ wl, const float* __restrict__ wr,
                        uint32_t* __restrict__ bh, uint32_t* __restrict__ blo, int NT) {
    int idx = blockIdx.x * blockDim.x + threadIdx.x;
    if (idx >= 16 * NT * 32) return;
    int l = idx & 31;
    int kn = idx >> 5;
    int nt = kn % NT;
    int ks = kn / NT;
    int n = nt * 8 + (l >> 2);
#pragma unroll
    for (int r = 0; r < 2; r++) {
        int k = ks * 16 + 2 * (l & 3) + 8 * r;
        float v0 = (k < 128) ? wl[n * 128 + k] : wr[n * 128 + (k - 128)];
        float v1 = (k + 1 < 128) ? wl[n * 128 + k + 1] : wr[n * 128 + (k + 1 - 128)];
        uint32_t h, lo2;
        split2(v0, v1, h, lo2);
        bh[((ks * NT + nt) * 32 + l) * 2 + r] = h;
        blo[((ks * NT + nt) * 32 + l) * 2 + r] = lo2;
    }
}

__device__ __forceinline__ void mma16816(float* c, const uint4& a, uint32_t b0, uint32_t b1) {
    asm volatile(
        "mma.sync.aligned.m16n8k16.row.col.f32.bf16.bf16.f32 "
        "{%0,%1,%2,%3}, {%4,%5,%6,%7}, {%8,%9}, {%0,%1,%2,%3};"
        : "+f"(c[0]), "+f"(c[1]), "+f"(c[2]), "+f"(c[3])
        : "r"(a.x), "r"(a.y), "r"(a.z), "r"(a.w), "r"(b0), "r"(b1));
}

// GEMM: out[N x OUTN] = [mean|X] @ W^T + b (+relu/dropout).
// CTA = 256 thr = 8 warps; warp = one 16-row m-tile x all OUTN cols.
// A frags from gmem image (coalesced v4), B frags from smem (conflict-free lds.64).
// 3 mma per (ks, nt): Ah*Bh + Ah*Bl + Al*Bh.
template<int OUTN, bool DROP>
__global__ __launch_bounds__(256)
void k_mma(const uint32_t* __restrict__ Bh, const uint32_t* __restrict__ Bl,
           const float* __restrict__ bias, const float* __restrict__ u,
           float* __restrict__ out, int nmt, int N) {
    constexpr int NT = OUTN / 8;
    constexpr int BW = 16 * NT * 64;               // u32 per image
    extern __shared__ uint32_t bs[];
    uint32_t* bsh = bs;
    uint32_t* bsl = bs + BW;

    const int tid = threadIdx.x;
    {
        const uint4* gh = (const uint4*)Bh;
        const uint4* gl = (const uint4*)Bl;
        uint4* s0 = (uint4*)bsh;
        uint4* s1 = (uint4*)bsl;
#pragma unroll
        for (int i = tid; i < BW / 4; i += 256) { s0[i] = gh[i]; s1[i] = gl[i]; }
    }
    __syncthreads();

    const int wid = tid >> 5, lane = tid & 31;
    const int mt = blockIdx.x * 8 + wid;
    if (mt >= nmt) return;

    float acc[NT][4];
#pragma unroll
    for (int nt = 0; nt < NT; nt++)
#pragma unroll
        for (int i = 0; i < 4; i++) acc[nt][i] = 0.f;

    const uint4* pah = ((const uint4*)g_ah) + (size_t)mt * 16 * 32 + lane;
    const uint4* pal = ((const uint4*)g_al) + (size_t)mt * 16 * 32 + lane;
    const uint2* sh2 = ((const uint2*)bsh) + lane;
    const uint2* sl2 = ((const uint2*)bsl) + lane;

#pragma unroll 1
    for (int ks = 0; ks < 16; ks++) {
        uint4 ah = pah[ks * 32];
        uint4 al = pal[ks * 32];
#pragma unroll
        for (int nt = 0; nt < NT; nt++) {
            uint2 wh = sh2[(ks * NT + nt) * 32];
            uint2 wlo = sl2[(ks * NT + nt) * 32];
            mma16816(acc[nt], ah, wh.x, wh.y);
            mma16816(acc[nt], ah, wlo.x, wlo.y);
            mma16816(acc[nt], al, wh.x, wh.y);
        }
    }

    // Epilogue: c0,c1 = row g cols (2t,2t+1); c2,c3 = row g+8.
    const int g = lane >> 2, t = lane & 3;
    const int r0 = mt * 16 + g;
    const int r1 = r0 + 8;
    const bool ok0 = r0 < N, ok1 = r1 < N;
    const float kinv = 1.0f / 0.7f;
#pragma unroll
    for (int nt = 0; nt < NT; nt++) {
        int c0 = nt * 8 + 2 * t;
        float2 b2 = *(const float2*)(bias + c0);
        float v0 = acc[nt][0] + b2.x, v1 = acc[nt][1] + b2.y;
        float v2 = acc[nt][2] + b2.x, v3 = acc[nt][3] + b2.y;
        if (DROP) {
            if (ok0) {
                float2 uu = *(const float2*)(u + (size_t)r0 * OUTN + c0);
                v0 = (v0 > 0.f ? v0 : 0.f) * (uu.x >= 0.3f ? kinv : 0.f);
                v1 = (v1 > 0.f ? v1 : 0.f) * (uu.y >= 0.3f ? kinv : 0.f);
            }
            if (ok1) {
                float2 uu = *(const float2*)(u + (size_t)r1 * OUTN + c0);
                v2 = (v2 > 0.f ? v2 : 0.f) * (uu.x >= 0.3f ? kinv : 0.f);
                v3 = (v3 > 0.f ? v3 : 0.f) * (uu.y >= 0.3f ? kinv : 0.f);
            }
        }
        if (ok0) *(float2*)(out + (size_t)r0 * OUTN + c0) = make_float2(v0, v1);
        if (ok1) *(float2*)(out + (size_t)r1 * OUTN + c0) = make_float2(v2, v3);
    }
}

extern "C" void kernel_launch(void* const* d_in, const int* in_sizes, int n_in,
                              void* d_out, int out_size) {
    const float* x   = (const float*)d_in[0];
    const float* u1  = (const float*)d_in[1];
    const float* u2  = (const float*)d_in[2];
    const float* wl0 = (const float*)d_in[3];
    const float* bl0 = (const float*)d_in[4];
    const float* wr0 = (const float*)d_in[5];
    const float* wl1 = (const float*)d_in[6];
    const float* bl1 = (const float*)d_in[7];
    const float* wr1 = (const float*)d_in[8];
    const float* wl2 = (const float*)d_in[9];
    const float* bl2 = (const float*)d_in[10];
    const float* wr2 = (const float*)d_in[11];
    const int*   ei  = (const int*)d_in[12];

    const int N = in_sizes[0] / DH;
    const int E = in_sizes[12] / 2;
    const int* src = ei;
    const int* dst = ei + E;
    float* out = (float*)d_out;

    float* hbuf;
    uint32_t *bh, *bl;
    cudaGetSymbolAddress((void**)&hbuf, g_h);
    cudaGetSymbolAddress((void**)&bh, g_bh);
    cudaGetSymbolAddress((void**)&bl, g_bl);
    const int LSTRIDE = 16 * 16 * 32 * 2;

    const int smem128 = 2 * 16 * 16 * 64 * 4;   // 128 KB
    const int smem64  = 2 * 16 * 8 * 64 * 4;    // 64 KB
    cudaFuncSetAttribute(k_mma<128, true>,
                         cudaFuncAttributeMaxDynamicSharedMemorySize, smem128);
    cudaFuncSetAttribute(k_mma<64, false>,
                         cudaFuncAttributeMaxDynamicSharedMemorySize, smem64);

    const int tb = 256;
    const int nmt = (N + 15) / 16;
    const int gw = (N * 32 + tb - 1) / tb;        // gather: warp per node
    const int gp = (nmt * 16 * 32 + tb - 1) / tb; // prep grid
    const int gg = (nmt + 7) / 8;                 // gemm grid

    // CSR build (once, reused by all 3 layers)
    k_zero_cnt<<<(N + tb - 1) / tb, tb>>>(N);
    k_count<<<(E + tb - 1) / tb, tb>>>(dst, E);
    k_scan<<<1, 1024>>>(N);
    k_fill<<<(E + tb - 1) / tb, tb>>>(src, dst, E);

    // Weight fragment images (once)
    k_wtimg<<<(16 * 16 * 32 + tb - 1) / tb, tb>>>(wl0, wr0, bh + 0 * LSTRIDE, bl + 0 * LSTRIDE, 16);
    k_wtimg<<<(16 * 16 * 32 + tb - 1) / tb, tb>>>(wl1, wr1, bh + 1 * LSTRIDE, bl + 1 * LSTRIDE, 16);
    k_wtimg<<<(16 * 8 * 32 + tb - 1) / tb, tb>>>(wl2, wr2, bh + 2 * LSTRIDE, bl + 2 * LSTRIDE, 8);

    // Layer 0
    k_gather<<<gw, tb>>>(x, N);
    k_prep<<<gp, tb>>>(x, nmt, N);
    k_mma<128, true><<<gg, 256, smem128>>>(bh + 0 * LSTRIDE, bl + 0 * LSTRIDE, bl0, u1, hbuf, nmt, N);
    // Layer 1
    k_gather<<<gw, tb>>>(hbuf, N);
    k_prep<<<gp, tb>>>(hbuf, nmt, N);
    k_mma<128, true><<<gg, 256, smem128>>>(bh + 1 * LSTRIDE, bl + 1 * LSTRIDE, bl1, u2, hbuf, nmt, N);
    // Layer 2
    k_gather<<<gw, tb>>>(hbuf, N);
    k_prep<<<gp, tb>>>(hbuf, nmt, N);
    k_mma<64, false><<<gg, 256, smem64>>>(bh + 2 * LSTRIDE, bl + 2 * LSTRIDE, bl2, nullptr, out, nmt, N);
}

// round 8
// speedup vs baseline: 2.2321x; 1.1413x over previous
#include <cuda_runtime.h>
#include <cuda_bf16.h>
#include <cstdint>

#define NN 50000
#define EE 800000
#define NMT 3125           // ceil(50000/16)

// ---------------- scratch (__device__ globals; no allocs) ----------------
__device__ float g_pq[(size_t)NN * 256];   // [p|q] GEMM output (max 256 cols)
__device__ float g_inv[NN];
__device__ int   g_cnt[NN];
__device__ int   g_off[NN + 1];
__device__ int   g_cur[NN];
__device__ int   g_csr[EE];
// A fragment images (K=128): [mt][ks(8)][lane(32)][4 x b32] bf16x2
__device__ uint32_t g_ah[(size_t)NMT * 8 * 32 * 4];
__device__ uint32_t g_al[(size_t)NMT * 8 * 32 * 4];
// B fragment images: [ks(8)][nt(<=32)][lane(32)][2 x b32]
__device__ uint32_t g_bh[3][8 * 32 * 32 * 2];
__device__ uint32_t g_bl[3][8 * 32 * 32 * 2];

// ---------------- CSR build ----------------
__global__ void k_zero_cnt(int n) {
    int i = blockIdx.x * blockDim.x + threadIdx.x;
    if (i < n) g_cnt[i] = 0;
}
__global__ void k_count(const int* __restrict__ dst, int E) {
    int e = blockIdx.x * blockDim.x + threadIdx.x;
    if (e < E) atomicAdd(&g_cnt[dst[e]], 1);
}
__global__ void k_scan(int n) {
    __shared__ int part[1024];
    int t = threadIdx.x;
    int chunk = (n + 1023) >> 10;
    int lo = t * chunk, hi = min(lo + chunk, n);
    int s = 0;
    for (int i = lo; i < hi; i++) s += g_cnt[i];
    part[t] = s;
    __syncthreads();
    for (int d = 1; d < 1024; d <<= 1) {
        int v = (t >= d) ? part[t - d] : 0;
        __syncthreads();
        part[t] += v;
        __syncthreads();
    }
    int run = (t == 0) ? 0 : part[t - 1];
    for (int i = lo; i < hi; i++) {
        int c = g_cnt[i];
        g_off[i] = run;
        g_cur[i] = run;
        g_inv[i] = 1.0f / (float)max(c, 1);
        run += c;
    }
    if (t == 1023) g_off[n] = run;
}
__global__ void k_fill(const int* __restrict__ src, const int* __restrict__ dst, int E) {
    int e = blockIdx.x * blockDim.x + threadIdx.x;
    if (e < E) {
        int p = atomicAdd(&g_cur[dst[e]], 1);
        g_csr[p] = src[e];
    }
}

// ---------------- bf16 helpers ----------------
__device__ __forceinline__ void split2(float a, float b, uint32_t& hi, uint32_t& lo) {
    __nv_bfloat162 h = __floats2bfloat162_rn(a, b);
    hi = *reinterpret_cast<uint32_t*>(&h);
    float ra = a - __bfloat162float(h.x);
    float rb = b - __bfloat162float(h.y);
    __nv_bfloat162 l = __floats2bfloat162_rn(ra, rb);
    lo = *reinterpret_cast<uint32_t*>(&l);
}

// A fragment image from x (layer 0 only). idx = (mt*8 + ks)*32 + lane.
__global__ void k_prep0(const float* __restrict__ x, int nmt, int N) {
    int idx = blockIdx.x * blockDim.x + threadIdx.x;
    if (idx >= nmt * 8 * 32) return;
    int l = idx & 31;
    int mk = idx >> 5;
    int ks = mk & 7;
    int mt = mk >> 3;
    int R0 = mt * 16 + (l >> 2);
    int Kl = 2 * (l & 3) + ks * 16;
    uint32_t hi[4], lo[4];
#pragma unroll
    for (int rr = 0; rr < 2; rr++) {
        int row = R0 + 8 * rr;
        bool ok = row < N;
#pragma unroll
        for (int kk = 0; kk < 2; kk++) {
            float2 v = ok ? *(const float2*)(x + (size_t)row * 128 + Kl + 8 * kk)
                          : make_float2(0.f, 0.f);
            split2(v.x, v.y, hi[rr + 2 * kk], lo[rr + 2 * kk]);
        }
    }
    ((uint4*)g_ah)[idx] = make_uint4(hi[0], hi[1], hi[2], hi[3]);
    ((uint4*)g_al)[idx] = make_uint4(lo[0], lo[1], lo[2], lo[3]);
}

// B image for concatenated W2 = [wl; wr] (2*OUT rows x 128 k). NT = OUT/4 tiles.
__global__ void k_wtimg(const float* __restrict__ wl, const float* __restrict__ wr,
                        uint32_t* __restrict__ bh, uint32_t* __restrict__ blo, int OUT) {
    int NT = OUT / 4;
    int idx = blockIdx.x * blockDim.x + threadIdx.x;
    if (idx >= 8 * NT * 32) return;
    int l = idx & 31;
    int kn = idx >> 5;
    int nt = kn % NT;
    int ks = kn / NT;
    int n = nt * 8 + (l >> 2);
    const float* Wrow = (n < OUT) ? (wl + (size_t)n * 128) : (wr + (size_t)(n - OUT) * 128);
#pragma unroll
    for (int r = 0; r < 2; r++) {
        int k = ks * 16 + 2 * (l & 3) + 8 * r;
        uint32_t h, lo2;
        split2(Wrow[k], Wrow[k + 1], h, lo2);
        bh[((ks * NT + nt) * 32 + l) * 2 + r] = h;
        blo[((ks * NT + nt) * 32 + l) * 2 + r] = lo2;
    }
}

__device__ __forceinline__ void mma16816(float* c, const uint4& a, uint32_t b0, uint32_t b1) {
    asm volatile(
        "mma.sync.aligned.m16n8k16.row.col.f32.bf16.bf16.f32 "
        "{%0,%1,%2,%3}, {%4,%5,%6,%7}, {%8,%9}, {%0,%1,%2,%3};"
        : "+f"(c[0]), "+f"(c[1]), "+f"(c[2]), "+f"(c[3])
        : "r"(a.x), "r"(a.y), "r"(a.z), "r"(a.w), "r"(b0), "r"(b1));
}

// GEMM: pq[N x NT*8] = h(frag images, K=128) @ W2^T. 512 thr = 16 warps;
// warp = (mt-tile, column half). 3 mma per (ks,nt): Ah*Bh + Ah*Bl + Al*Bh.
template<int NT>
__global__ __launch_bounds__(512)
void k_mma(const uint32_t* __restrict__ Bh, const uint32_t* __restrict__ Bl,
           float* __restrict__ pq, int nmt, int N) {
    constexpr int BW = 8 * NT * 64;                // u32 per image
    constexpr int NTH = NT / 2;
    extern __shared__ uint32_t bs[];
    uint32_t* bsh = bs;
    uint32_t* bsl = bs + BW;

    const int tid = threadIdx.x;
    {
        const uint4* gh = (const uint4*)Bh;
        const uint4* gl = (const uint4*)Bl;
        uint4* s0 = (uint4*)bsh;
        uint4* s1 = (uint4*)bsl;
#pragma unroll
        for (int i = tid; i < BW / 4; i += 512) { s0[i] = gh[i]; s1[i] = gl[i]; }
    }
    __syncthreads();

    const int wid = tid >> 5, lane = tid & 31;
    const int mt = blockIdx.x * 8 + (wid >> 1);
    const int ntb = (wid & 1) * NTH;
    if (mt >= nmt) return;

    float acc[NTH][4];
#pragma unroll
    for (int nt = 0; nt < NTH; nt++)
#pragma unroll
        for (int i = 0; i < 4; i++) acc[nt][i] = 0.f;

    const uint4* pah = ((const uint4*)g_ah) + (size_t)mt * 8 * 32 + lane;
    const uint4* pal = ((const uint4*)g_al) + (size_t)mt * 8 * 32 + lane;
    const uint2* sh2 = ((const uint2*)bsh) + lane;
    const uint2* sl2 = ((const uint2*)bsl) + lane;

#pragma unroll 1
    for (int ks = 0; ks < 8; ks++) {
        uint4 ah = pah[ks * 32];
        uint4 al = pal[ks * 32];
#pragma unroll
        for (int nt = 0; nt < NTH; nt++) {
            int i2 = (ks * NT + ntb + nt) * 32;
            uint2 wh = sh2[i2];
            uint2 wlo = sl2[i2];
            mma16816(acc[nt], ah, wh.x, wh.y);
            mma16816(acc[nt], ah, wlo.x, wlo.y);
            mma16816(acc[nt], al, wh.x, wh.y);
        }
    }

    const int g = lane >> 2, t = lane & 3;
    const int r0 = mt * 16 + g, r1 = r0 + 8;
    const size_t C = NT * 8;
#pragma unroll
    for (int nt = 0; nt < NTH; nt++) {
        int c0 = (ntb + nt) * 8 + 2 * t;
        if (r0 < N) *(float2*)(pq + r0 * C + c0) = make_float2(acc[nt][0], acc[nt][1]);
        if (r1 < N) *(float2*)(pq + r1 * C + c0) = make_float2(acc[nt][2], acc[nt][3]);
    }
}

// Fused: y = inv*agg(p) + q + b (+relu/dropout) -> next-layer frag image, or final out.
// Block = one 16-row tile (512 thr, warp = row). pq row = [p(OUT) | q(OUT)].
template<int OUT, bool DROP, bool FRAGS>
__global__ __launch_bounds__(512)
void k_gatherep(const float* __restrict__ pq, const float* __restrict__ u,
                const float* __restrict__ bias, float* __restrict__ outp, int N) {
    __shared__ float yt[16][132];
    const int mt = blockIdx.x;
    const int tid = threadIdx.x;
    const int wid = tid >> 5, lane = tid & 31;
    const int r = mt * 16 + wid;
    const bool ok = r < N;
    const float4* P = (const float4*)pq;
    float4 y = make_float4(0.f, 0.f, 0.f, 0.f);

    if (OUT == 128) {
        const int c4 = lane;
        if (ok) {
            float4 s = make_float4(0.f, 0.f, 0.f, 0.f);
            int j = g_off[r], j1 = g_off[r + 1];
            for (; j + 1 < j1; j += 2) {
                int s0 = g_csr[j], s1 = g_csr[j + 1];
                float4 v0 = P[(size_t)s0 * 64 + c4];
                float4 v1 = P[(size_t)s1 * 64 + c4];
                s.x += v0.x + v1.x; s.y += v0.y + v1.y;
                s.z += v0.z + v1.z; s.w += v0.w + v1.w;
            }
            if (j < j1) {
                float4 v = P[(size_t)g_csr[j] * 64 + c4];
                s.x += v.x; s.y += v.y; s.z += v.z; s.w += v.w;
            }
            float iv = g_inv[r];
            float4 q = P[(size_t)r * 64 + 32 + c4];
            float4 b = ((const float4*)bias)[c4];
            y.x = iv * s.x + q.x + b.x;
            y.y = iv * s.y + q.y + b.y;
            y.z = iv * s.z + q.z + b.z;
            y.w = iv * s.w + q.w + b.w;
            if (DROP) {
                const float kinv = 1.0f / 0.7f;
                float4 uu = ((const float4*)u)[(size_t)r * 32 + c4];
                y.x = (y.x > 0.f ? y.x : 0.f) * (uu.x >= 0.3f ? kinv : 0.f);
                y.y = (y.y > 0.f ? y.y : 0.f) * (uu.y >= 0.3f ? kinv : 0.f);
                y.z = (y.z > 0.f ? y.z : 0.f) * (uu.z >= 0.3f ? kinv : 0.f);
                y.w = (y.w > 0.f ? y.w : 0.f) * (uu.w >= 0.3f ? kinv : 0.f);
            }
        }
        if (FRAGS) {
            yt[wid][c4 * 4 + 0] = y.x;
            yt[wid][c4 * 4 + 1] = y.y;
            yt[wid][c4 * 4 + 2] = y.z;
            yt[wid][c4 * 4 + 3] = y.w;
        } else if (ok) {
            ((float4*)outp)[(size_t)r * 32 + c4] = y;
        }
    } else {  // OUT == 64: half-warps split even/odd neighbors, shfl combine
        const int c4 = lane & 15;
        const int par = lane >> 4;
        float4 s = make_float4(0.f, 0.f, 0.f, 0.f);
        if (ok) {
            int j1 = g_off[r + 1];
            for (int j = g_off[r] + par; j < j1; j += 2) {
                float4 v = P[(size_t)g_csr[j] * 32 + c4];
                s.x += v.x; s.y += v.y; s.z += v.z; s.w += v.w;
            }
        }
        s.x += __shfl_xor_sync(0xFFFFFFFFu, s.x, 16);
        s.y += __shfl_xor_sync(0xFFFFFFFFu, s.y, 16);
        s.z += __shfl_xor_sync(0xFFFFFFFFu, s.z, 16);
        s.w += __shfl_xor_sync(0xFFFFFFFFu, s.w, 16);
        if (ok && par == 0) {
            float iv = g_inv[r];
            float4 q = P[(size_t)r * 32 + 16 + c4];
            float4 b = ((const float4*)bias)[c4];
            y.x = iv * s.x + q.x + b.x;
            y.y = iv * s.y + q.y + b.y;
            y.z = iv * s.z + q.z + b.z;
            y.w = iv * s.w + q.w + b.w;
            ((float4*)outp)[(size_t)r * 16 + c4] = y;
        }
    }

    if (FRAGS) {
        __syncthreads();
        const int base = mt * 1024;
#pragma unroll
        for (int i = tid; i < 1024; i += 512) {
            int ks = i >> 7, l = (i >> 2) & 31, reg = i & 3;
            int gg = (l >> 2) + 8 * (reg & 1);
            int c = 2 * (l & 3) + 16 * ks + 8 * (reg >> 1);
            uint32_t h, lo2;
            split2(yt[gg][c], yt[gg][c + 1], h, lo2);
            g_ah[base + i] = h;
            g_al[base + i] = lo2;
        }
    }
}

extern "C" void kernel_launch(void* const* d_in, const int* in_sizes, int n_in,
                              void* d_out, int out_size) {
    const float* x   = (const float*)d_in[0];
    const float* u1  = (const float*)d_in[1];
    const float* u2  = (const float*)d_in[2];
    const float* wl0 = (const float*)d_in[3];
    const float* bl0 = (const float*)d_in[4];
    const float* wr0 = (const float*)d_in[5];
    const float* wl1 = (const float*)d_in[6];
    const float* bl1 = (const float*)d_in[7];
    const float* wr1 = (const float*)d_in[8];
    const float* wl2 = (const float*)d_in[9];
    const float* bl2 = (const float*)d_in[10];
    const float* wr2 = (const float*)d_in[11];
    const int*   ei  = (const int*)d_in[12];

    const int N = in_sizes[0] / 128;
    const int E = in_sizes[12] / 2;
    const int* src = ei;
    const int* dst = ei + E;
    float* out = (float*)d_out;

    float* pq;
    uint32_t *bh, *bl;
    cudaGetSymbolAddress((void**)&pq, g_pq);
    cudaGetSymbolAddress((void**)&bh, g_bh);
    cudaGetSymbolAddress((void**)&bl, g_bl);
    const int LS = 8 * 32 * 32 * 2;

    const int smem32 = 2 * 8 * 32 * 64 * 4;   // 128 KB
    const int smem16 = 2 * 8 * 16 * 64 * 4;   // 64 KB
    cudaFuncSetAttribute(k_mma<32>, cudaFuncAttributeMaxDynamicSharedMemorySize, smem32);
    cudaFuncSetAttribute(k_mma<16>, cudaFuncAttributeMaxDynamicSharedMemorySize, smem16);

    const int tb = 256;
    const int nmt = (N + 15) / 16;
    const int gg = (nmt + 7) / 8;

    // CSR build
    k_zero_cnt<<<(N + tb - 1) / tb, tb>>>(N);
    k_count<<<(E + tb - 1) / tb, tb>>>(dst, E);
    k_scan<<<1, 1024>>>(N);
    k_fill<<<(E + tb - 1) / tb, tb>>>(src, dst, E);

    // Weight images ([wl;wr] concat, K=128)
    k_wtimg<<<(8 * 32 * 32 + tb - 1) / tb, tb>>>(wl0, wr0, bh + 0 * LS, bl + 0 * LS, 128);
    k_wtimg<<<(8 * 32 * 32 + tb - 1) / tb, tb>>>(wl1, wr1, bh + 1 * LS, bl + 1 * LS, 128);
    k_wtimg<<<(8 * 16 * 32 + tb - 1) / tb, tb>>>(wl2, wr2, bh + 2 * LS, bl + 2 * LS, 64);

    // Layer-0 A fragments from x
    k_prep0<<<(nmt * 8 * 32 + tb - 1) / tb, tb>>>(x, nmt, N);

    // Layer 0: GEMM -> [p|q], fused agg+epilogue -> frags(h1)
    k_mma<32><<<gg, 512, smem32>>>(bh + 0 * LS, bl + 0 * LS, pq, nmt, N);
    k_gatherep<128, true, true><<<nmt, 512>>>(pq, u1, bl0, nullptr, N);
    // Layer 1
    k_mma<32><<<gg, 512, smem32>>>(bh + 1 * LS, bl + 1 * LS, pq, nmt, N);
    k_gatherep<128, true, true><<<nmt, 512>>>(pq, u2, bl1, nullptr, N);
    // Layer 2: OUT=64, final output
    k_mma<16><<<gg, 512, smem16>>>(bh + 2 * LS, bl + 2 * LS, pq, nmt, N);
    k_gatherep<64, false, false><<<nmt, 512>>>(pq, nullptr, bl2, out, N);
}

// round 9
// speedup vs baseline: 2.2883x; 1.0252x over previous
#include <cuda_runtime.h>
#include <cuda_bf16.h>
#include <cuda_fp16.h>
#include <cstdint>

#define NN 50000
#define EE 800000
#define NMT 3125           // ceil(50000/16)

// ---------------- scratch (__device__ globals; no allocs) ----------------
// pq row layout (per node): p = OUT halves (fp16), then q = OUT floats (fp32).
// OUT=128 -> 768 B/row; OUT=64 -> 384 B/row. Allocated for the max.
__device__ __align__(16) unsigned char g_pq[(size_t)NN * 768];
__device__ float g_inv[NN];
__device__ int   g_cnt[NN];
__device__ int   g_off[NN + 1];
__device__ int   g_cur[NN];
__device__ int   g_csr[EE];
// A fragment images (K=128): [mt][ks(8)][lane(32)][4 x b32] bf16x2
__device__ uint32_t g_ah[(size_t)NMT * 8 * 32 * 4];
__device__ uint32_t g_al[(size_t)NMT * 8 * 32 * 4];
// B fragment images: [ks(8)][nt(<=32)][lane(32)][2 x b32]
__device__ uint32_t g_bh[3][8 * 32 * 32 * 2];
__device__ uint32_t g_bl[3][8 * 32 * 32 * 2];

// ---------------- CSR build ----------------
__global__ void k_zero_cnt(int n) {
    int i = blockIdx.x * blockDim.x + threadIdx.x;
    if (i < n) g_cnt[i] = 0;
}
__global__ void k_count(const int* __restrict__ dst, int E) {
    int e = blockIdx.x * blockDim.x + threadIdx.x;
    if (e < E) atomicAdd(&g_cnt[dst[e]], 1);
}
__global__ void k_scan(int n) {
    __shared__ int part[1024];
    int t = threadIdx.x;
    int chunk = (n + 1023) >> 10;
    int lo = t * chunk, hi = min(lo + chunk, n);
    int s = 0;
    for (int i = lo; i < hi; i++) s += g_cnt[i];
    part[t] = s;
    __syncthreads();
    for (int d = 1; d < 1024; d <<= 1) {
        int v = (t >= d) ? part[t - d] : 0;
        __syncthreads();
        part[t] += v;
        __syncthreads();
    }
    int run = (t == 0) ? 0 : part[t - 1];
    for (int i = lo; i < hi; i++) {
        int c = g_cnt[i];
        g_off[i] = run;
        g_cur[i] = run;
        g_inv[i] = 1.0f / (float)max(c, 1);
        run += c;
    }
    if (t == 1023) g_off[n] = run;
}
__global__ void k_fill(const int* __restrict__ src, const int* __restrict__ dst, int E) {
    int e = blockIdx.x * blockDim.x + threadIdx.x;
    if (e < E) {
        int p = atomicAdd(&g_cur[dst[e]], 1);
        g_csr[p] = src[e];
    }
}

// ---------------- bf16 helpers ----------------
__device__ __forceinline__ void split2(float a, float b, uint32_t& hi, uint32_t& lo) {
    __nv_bfloat162 h = __floats2bfloat162_rn(a, b);
    hi = *reinterpret_cast<uint32_t*>(&h);
    float ra = a - __bfloat162float(h.x);
    float rb = b - __bfloat162float(h.y);
    __nv_bfloat162 l = __floats2bfloat162_rn(ra, rb);
    lo = *reinterpret_cast<uint32_t*>(&l);
}

// A fragment image from x (layer 0 only).
__global__ void k_prep0(const float* __restrict__ x, int nmt, int N) {
    int idx = blockIdx.x * blockDim.x + threadIdx.x;
    if (idx >= nmt * 8 * 32) return;
    int l = idx & 31;
    int mk = idx >> 5;
    int ks = mk & 7;
    int mt = mk >> 3;
    int R0 = mt * 16 + (l >> 2);
    int Kl = 2 * (l & 3) + ks * 16;
    uint32_t hi[4], lo[4];
#pragma unroll
    for (int rr = 0; rr < 2; rr++) {
        int row = R0 + 8 * rr;
        bool ok = row < N;
#pragma unroll
        for (int kk = 0; kk < 2; kk++) {
            float2 v = ok ? *(const float2*)(x + (size_t)row * 128 + Kl + 8 * kk)
                          : make_float2(0.f, 0.f);
            split2(v.x, v.y, hi[rr + 2 * kk], lo[rr + 2 * kk]);
        }
    }
    ((uint4*)g_ah)[idx] = make_uint4(hi[0], hi[1], hi[2], hi[3]);
    ((uint4*)g_al)[idx] = make_uint4(lo[0], lo[1], lo[2], lo[3]);
}

// B image for concatenated W2 = [wl; wr] (2*OUT rows x 128 k). NT = OUT/4 tiles.
__global__ void k_wtimg(const float* __restrict__ wl, const float* __restrict__ wr,
                        uint32_t* __restrict__ bh, uint32_t* __restrict__ blo, int OUT) {
    int NT = OUT / 4;
    int idx = blockIdx.x * blockDim.x + threadIdx.x;
    if (idx >= 8 * NT * 32) return;
    int l = idx & 31;
    int kn = idx >> 5;
    int nt = kn % NT;
    int ks = kn / NT;
    int n = nt * 8 + (l >> 2);
    const float* Wrow = (n < OUT) ? (wl + (size_t)n * 128) : (wr + (size_t)(n - OUT) * 128);
#pragma unroll
    for (int r = 0; r < 2; r++) {
        int k = ks * 16 + 2 * (l & 3) + 8 * r;
        uint32_t h, lo2;
        split2(Wrow[k], Wrow[k + 1], h, lo2);
        bh[((ks * NT + nt) * 32 + l) * 2 + r] = h;
        blo[((ks * NT + nt) * 32 + l) * 2 + r] = lo2;
    }
}

__device__ __forceinline__ void mma16816(float* c, const uint4& a, uint32_t b0, uint32_t b1) {
    asm volatile(
        "mma.sync.aligned.m16n8k16.row.col.f32.bf16.bf16.f32 "
        "{%0,%1,%2,%3}, {%4,%5,%6,%7}, {%8,%9}, {%0,%1,%2,%3};"
        : "+f"(c[0]), "+f"(c[1]), "+f"(c[2]), "+f"(c[3])
        : "r"(a.x), "r"(a.y), "r"(a.z), "r"(a.w), "r"(b0), "r"(b1));
}

// GEMM: [p|q] = h(frag images, K=128) @ [wl;wr]^T.  512 thr = 16 warps;
// warp = (mt-tile, column half). Warp 0-half covers cols<OUT (p, fp16 store),
// warp 1-half covers cols>=OUT (q, fp32 store). 3 mma per (ks,nt).
template<int NT>
__global__ __launch_bounds__(512)
void k_mma(const uint32_t* __restrict__ Bh, const uint32_t* __restrict__ Bl,
           unsigned char* __restrict__ pq, int nmt, int N) {
    constexpr int BW = 8 * NT * 64;                // u32 per image
    constexpr int NTH = NT / 2;
    constexpr int OUT = NT * 4;
    constexpr int ROWB = OUT * 6;                  // bytes per pq row
    extern __shared__ uint32_t bs[];
    uint32_t* bsh = bs;
    uint32_t* bsl = bs + BW;

    const int tid = threadIdx.x;
    {
        const uint4* gh = (const uint4*)Bh;
        const uint4* gl = (const uint4*)Bl;
        uint4* s0 = (uint4*)bsh;
        uint4* s1 = (uint4*)bsl;
#pragma unroll
        for (int i = tid; i < BW / 4; i += 512) { s0[i] = gh[i]; s1[i] = gl[i]; }
    }
    __syncthreads();

    const int wid = tid >> 5, lane = tid & 31;
    const int mt = blockIdx.x * 8 + (wid >> 1);
    const int ntb = (wid & 1) * NTH;
    if (mt >= nmt) return;

    float acc[NTH][4];
#pragma unroll
    for (int nt = 0; nt < NTH; nt++)
#pragma unroll
        for (int i = 0; i < 4; i++) acc[nt][i] = 0.f;

    const uint4* pah = ((const uint4*)g_ah) + (size_t)mt * 8 * 32 + lane;
    const uint4* pal = ((const uint4*)g_al) + (size_t)mt * 8 * 32 + lane;
    const uint2* sh2 = ((const uint2*)bsh) + lane;
    const uint2* sl2 = ((const uint2*)bsl) + lane;

#pragma unroll 1
    for (int ks = 0; ks < 8; ks++) {
        uint4 ah = pah[ks * 32];
        uint4 al = pal[ks * 32];
#pragma unroll
        for (int nt = 0; nt < NTH; nt++) {
            int i2 = (ks * NT + ntb + nt) * 32;
            uint2 wh = sh2[i2];
            uint2 wlo = sl2[i2];
            mma16816(acc[nt], ah, wh.x, wh.y);
            mma16816(acc[nt], ah, wlo.x, wlo.y);
            mma16816(acc[nt], al, wh.x, wh.y);
        }
    }

    const int g = lane >> 2, t = lane & 3;
    const int r0 = mt * 16 + g, r1 = r0 + 8;
    const bool ok0 = r0 < N, ok1 = r1 < N;
#pragma unroll
    for (int nt = 0; nt < NTH; nt++) {
        int col = (ntb + nt) * 8 + 2 * t;
        if (col < OUT) {    // p: fp16 store (uniform per warp)
            if (ok0) *(__half2*)(pq + (size_t)r0 * ROWB + col * 2)
                         = __floats2half2_rn(acc[nt][0], acc[nt][1]);
            if (ok1) *(__half2*)(pq + (size_t)r1 * ROWB + col * 2)
                         = __floats2half2_rn(acc[nt][2], acc[nt][3]);
        } else {            // q: fp32 store
            int qc = col - OUT;
            if (ok0) *(float2*)(pq + (size_t)r0 * ROWB + OUT * 2 + qc * 4)
                         = make_float2(acc[nt][0], acc[nt][1]);
            if (ok1) *(float2*)(pq + (size_t)r1 * ROWB + OUT * 2 + qc * 4)
                         = make_float2(acc[nt][2], acc[nt][3]);
        }
    }
}

// Fused: y = inv*agg(p_fp16) + q + b (+relu/dropout) -> next-layer frag image or out.
// Block = one 16-row tile (512 thr, warp = row).
template<int OUT, bool DROP, bool FRAGS>
__global__ __launch_bounds__(512)
void k_gatherep(const unsigned char* __restrict__ pq, const float* __restrict__ u,
                const float* __restrict__ bias, float* __restrict__ outp, int N) {
    __shared__ float yt[16][132];
    constexpr int ROWB = OUT * 6;
    const int mt = blockIdx.x;
    const int tid = threadIdx.x;
    const int wid = tid >> 5, lane = tid & 31;
    const int r = mt * 16 + wid;
    const bool ok = r < N;

    if (OUT == 128) {
        // lane covers cols lane*4..lane*4+3; p load = uint2 (4 halves)
        float4 y = make_float4(0.f, 0.f, 0.f, 0.f);
        if (ok) {
            float4 sA = make_float4(0.f, 0.f, 0.f, 0.f);
            float4 sB = make_float4(0.f, 0.f, 0.f, 0.f);
            int j = g_off[r], j1 = g_off[r + 1];
            for (; j + 3 < j1; j += 4) {
                int s0 = g_csr[j], s1 = g_csr[j + 1], s2 = g_csr[j + 2], s3 = g_csr[j + 3];
                uint2 a = *((const uint2*)(pq + (size_t)s0 * ROWB) + lane);
                uint2 b = *((const uint2*)(pq + (size_t)s1 * ROWB) + lane);
                uint2 c = *((const uint2*)(pq + (size_t)s2 * ROWB) + lane);
                uint2 d = *((const uint2*)(pq + (size_t)s3 * ROWB) + lane);
                float2 a0 = __half22float2(*(__half2*)&a.x), a1 = __half22float2(*(__half2*)&a.y);
                float2 b0 = __half22float2(*(__half2*)&b.x), b1 = __half22float2(*(__half2*)&b.y);
                float2 c0 = __half22float2(*(__half2*)&c.x), c1 = __half22float2(*(__half2*)&c.y);
                float2 d0 = __half22float2(*(__half2*)&d.x), d1 = __half22float2(*(__half2*)&d.y);
                sA.x += a0.x + c0.x; sA.y += a0.y + c0.y; sA.z += a1.x + c1.x; sA.w += a1.y + c1.y;
                sB.x += b0.x + d0.x; sB.y += b0.y + d0.y; sB.z += b1.x + d1.x; sB.w += b1.y + d1.y;
            }
            for (; j < j1; j++) {
                int s0 = g_csr[j];
                uint2 a = *((const uint2*)(pq + (size_t)s0 * ROWB) + lane);
                float2 a0 = __half22float2(*(__half2*)&a.x), a1 = __half22float2(*(__half2*)&a.y);
                sA.x += a0.x; sA.y += a0.y; sA.z += a1.x; sA.w += a1.y;
            }
            float iv = g_inv[r];
            float4 q = ((const float4*)(pq + (size_t)r * ROWB + OUT * 2))[lane];
            float4 b = ((const float4*)bias)[lane];
            y.x = iv * (sA.x + sB.x) + q.x + b.x;
            y.y = iv * (sA.y + sB.y) + q.y + b.y;
            y.z = iv * (sA.z + sB.z) + q.z + b.z;
            y.w = iv * (sA.w + sB.w) + q.w + b.w;
            if (DROP) {
                const float kinv = 1.0f / 0.7f;
                float4 uu = ((const float4*)u)[(size_t)r * 32 + lane];
                y.x = (y.x > 0.f ? y.x : 0.f) * (uu.x >= 0.3f ? kinv : 0.f);
                y.y = (y.y > 0.f ? y.y : 0.f) * (uu.y >= 0.3f ? kinv : 0.f);
                y.z = (y.z > 0.f ? y.z : 0.f) * (uu.z >= 0.3f ? kinv : 0.f);
                y.w = (y.w > 0.f ? y.w : 0.f) * (uu.w >= 0.3f ? kinv : 0.f);
            }
        }
        if (FRAGS) {
            yt[wid][lane * 4 + 0] = y.x;
            yt[wid][lane * 4 + 1] = y.y;
            yt[wid][lane * 4 + 2] = y.z;
            yt[wid][lane * 4 + 3] = y.w;
        } else if (ok) {
            ((float4*)outp)[(size_t)r * 32 + lane] = y;
        }
    } else {  // OUT == 64: lane covers cols 2*lane..2*lane+1; p load = uint (half2)
        if (ok) {
            float2 sA = make_float2(0.f, 0.f), sB = make_float2(0.f, 0.f);
            int j = g_off[r], j1 = g_off[r + 1];
            for (; j + 3 < j1; j += 4) {
                int s0 = g_csr[j], s1 = g_csr[j + 1], s2 = g_csr[j + 2], s3 = g_csr[j + 3];
                float2 a = __half22float2(*((const __half2*)(pq + (size_t)s0 * ROWB) + lane));
                float2 b = __half22float2(*((const __half2*)(pq + (size_t)s1 * ROWB) + lane));
                float2 c = __half22float2(*((const __half2*)(pq + (size_t)s2 * ROWB) + lane));
                float2 d = __half22float2(*((const __half2*)(pq + (size_t)s3 * ROWB) + lane));
                sA.x += a.x + c.x; sA.y += a.y + c.y;
                sB.x += b.x + d.x; sB.y += b.y + d.y;
            }
            for (; j < j1; j++) {
                float2 a = __half22float2(*((const __half2*)(pq + (size_t)g_csr[j] * ROWB) + lane));
                sA.x += a.x; sA.y += a.y;
            }
            float iv = g_inv[r];
            float2 q = ((const float2*)(pq + (size_t)r * ROWB + OUT * 2))[lane];
            float2 b = ((const float2*)bias)[lane];
            float2 y;
            y.x = iv * (sA.x + sB.x) + q.x + b.x;
            y.y = iv * (sA.y + sB.y) + q.y + b.y;
            ((float2*)outp)[(size_t)r * 32 + lane] = y;
        }
    }

    if (FRAGS) {
        __syncthreads();
        const int base = mt * 1024;
#pragma unroll
        for (int i = tid; i < 1024; i += 512) {
            int ks = i >> 7, l = (i >> 2) & 31, reg = i & 3;
            int gg = (l >> 2) + 8 * (reg & 1);
            int c = 2 * (l & 3) + 16 * ks + 8 * (reg >> 1);
            uint32_t h, lo2;
            split2(yt[gg][c], yt[gg][c + 1], h, lo2);
            g_ah[base + i] = h;
            g_al[base + i] = lo2;
        }
    }
}

extern "C" void kernel_launch(void* const* d_in, const int* in_sizes, int n_in,
                              void* d_out, int out_size) {
    const float* x   = (const float*)d_in[0];
    const float* u1  = (const float*)d_in[1];
    const float* u2  = (const float*)d_in[2];
    const float* wl0 = (const float*)d_in[3];
    const float* bl0 = (const float*)d_in[4];
    const float* wr0 = (const float*)d_in[5];
    const float* wl1 = (const float*)d_in[6];
    const float* bl1 = (const float*)d_in[7];
    const float* wr1 = (const float*)d_in[8];
    const float* wl2 = (const float*)d_in[9];
    const float* bl2 = (const float*)d_in[10];
    const float* wr2 = (const float*)d_in[11];
    const int*   ei  = (const int*)d_in[12];

    const int N = in_sizes[0] / 128;
    const int E = in_sizes[12] / 2;
    const int* src = ei;
    const int* dst = ei + E;
    float* out = (float*)d_out;

    unsigned char* pq;
    uint32_t *bh, *bl;
    cudaGetSymbolAddress((void**)&pq, g_pq);
    cudaGetSymbolAddress((void**)&bh, g_bh);
    cudaGetSymbolAddress((void**)&bl, g_bl);
    const int LS = 8 * 32 * 32 * 2;

    const int smem32 = 2 * 8 * 32 * 64 * 4;   // 128 KB
    const int smem16 = 2 * 8 * 16 * 64 * 4;   // 64 KB
    cudaFuncSetAttribute(k_mma<32>, cudaFuncAttributeMaxDynamicSharedMemorySize, smem32);
    cudaFuncSetAttribute(k_mma<16>, cudaFuncAttributeMaxDynamicSharedMemorySize, smem16);

    const int tb = 256;
    const int nmt = (N + 15) / 16;
    const int gg = (nmt + 7) / 8;

    // CSR build
    k_zero_cnt<<<(N + tb - 1) / tb, tb>>>(N);
    k_count<<<(E + tb - 1) / tb, tb>>>(dst, E);
    k_scan<<<1, 1024>>>(N);
    k_fill<<<(E + tb - 1) / tb, tb>>>(src, dst, E);

    // Weight images ([wl;wr] concat, K=128)
    k_wtimg<<<(8 * 32 * 32 + tb - 1) / tb, tb>>>(wl0, wr0, bh + 0 * LS, bl + 0 * LS, 128);
    k_wtimg<<<(8 * 32 * 32 + tb - 1) / tb, tb>>>(wl1, wr1, bh + 1 * LS, bl + 1 * LS, 128);
    k_wtimg<<<(8 * 16 * 32 + tb - 1) / tb, tb>>>(wl2, wr2, bh + 2 * LS, bl + 2 * LS, 64);

    // Layer-0 A fragments from x
    k_prep0<<<(nmt * 8 * 32 + tb - 1) / tb, tb>>>(x, nmt, N);

    // Layer 0
    k_mma<32><<<gg, 512, smem32>>>(bh + 0 * LS, bl + 0 * LS, pq, nmt, N);
    k_gatherep<128, true, true><<<nmt, 512>>>(pq, u1, bl0, nullptr, N);
    // Layer 1
    k_mma<32><<<gg, 512, smem32>>>(bh + 1 * LS, bl + 1 * LS, pq, nmt, N);
    k_gatherep<128, true, true><<<nmt, 512>>>(pq, u2, bl1, nullptr, N);
    // Layer 2
    k_mma<16><<<gg, 512, smem16>>>(bh + 2 * LS, bl + 2 * LS, pq, nmt, N);
    k_gatherep<64, false, false><<<nmt, 512>>>(pq, nullptr, bl2, out, N);
}

// round 12
// speedup vs baseline: 3.1747x; 1.3874x over previous
#include <cuda_runtime.h>
#include <cuda_bf16.h>
#include <cuda_fp16.h>
#include <cstdint>

#define NN 50000
#define EE 800000
#define NMT 3125           // ceil(50000/16)

// ---------------- scratch (__device__ globals; no allocs) ----------------
// pq row layout (per node): p = OUT halves (fp16), then q = OUT floats (fp32).
__device__ __align__(16) unsigned char g_pq[(size_t)NN * 768];
__device__ float g_inv[NN];
__device__ int   g_cnt[NN];
__device__ int   g_off[NN + 1];
__device__ int   g_cur[NN];
__device__ int   g_csr[EE];
__device__ int   g_part[256];
__device__ int   g_poff[256];
// A fragment images (K=128): [mt][ks(8)][lane(32)][4 x b32] bf16x2
__device__ uint32_t g_ah[(size_t)NMT * 8 * 32 * 4];
__device__ uint32_t g_al[(size_t)NMT * 8 * 32 * 4];
// B fragment images: [ks(8)][nt(<=32)][lane(32)][2 x b32]
__device__ uint32_t g_bh[3][8 * 32 * 32 * 2];
__device__ uint32_t g_bl[3][8 * 32 * 32 * 2];

// ---------------- CSR build ----------------
__global__ void k_zero_cnt(int n) {
    int i = blockIdx.x * blockDim.x + threadIdx.x;
    if (i < n) g_cnt[i] = 0;
}
__global__ void k_count(const int* __restrict__ dst, int E) {
    int e = blockIdx.x * blockDim.x + threadIdx.x;
    if (e < E) atomicAdd(&g_cnt[dst[e]], 1);
}
// Phase 1: per-block (256 items) partial sums
__global__ void k_scan1(int n) {
    __shared__ int sh[256];
    int t = threadIdx.x;
    int i = blockIdx.x * 256 + t;
    sh[t] = (i < n) ? g_cnt[i] : 0;
    __syncthreads();
    for (int d = 128; d > 0; d >>= 1) {
        if (t < d) sh[t] += sh[t + d];
        __syncthreads();
    }
    if (t == 0) g_part[blockIdx.x] = sh[0];
}
// Phase 2: exclusive scan of partials (1 block, 256 threads)
__global__ void k_scan2(int nb) {
    __shared__ int sh[256];
    int t = threadIdx.x;
    int v = (t < nb) ? g_part[t] : 0;
    sh[t] = v;
    __syncthreads();
    for (int d = 1; d < 256; d <<= 1) {
        int u = (t >= d) ? sh[t - d] : 0;
        __syncthreads();
        sh[t] += u;
        __syncthreads();
    }
    if (t < nb) g_poff[t] = sh[t] - v;
}
// Phase 3: per-block exclusive scan + base; writes off/cur/inv
__global__ void k_scan3(int n) {
    __shared__ int sh[256];
    int t = threadIdx.x;
    int i = blockIdx.x * 256 + t;
    int c = (i < n) ? g_cnt[i] : 0;
    sh[t] = c;
    __syncthreads();
    for (int d = 1; d < 256; d <<= 1) {
        int u = (t >= d) ? sh[t - d] : 0;
        __syncthreads();
        sh[t] += u;
        __syncthreads();
    }
    int base = g_poff[blockIdx.x];
    if (i < n) {
        int excl = base + sh[t] - c;
        g_off[i] = excl;
        g_cur[i] = excl;
        g_inv[i] = 1.0f / (float)max(c, 1);
        if (i == n - 1) g_off[n] = base + sh[t];
    }
}
__global__ void k_fill(const int* __restrict__ src, const int* __restrict__ dst, int E) {
    int e = blockIdx.x * blockDim.x + threadIdx.x;
    if (e < E) {
        int p = atomicAdd(&g_cur[dst[e]], 1);
        g_csr[p] = src[e];
    }
}

// ---------------- bf16 helpers ----------------
__device__ __forceinline__ void split2(float a, float b, uint32_t& hi, uint32_t& lo) {
    __nv_bfloat162 h = __floats2bfloat162_rn(a, b);
    hi = *reinterpret_cast<uint32_t*>(&h);
    float ra = a - __bfloat162float(h.x);
    float rb = b - __bfloat162float(h.y);
    __nv_bfloat162 l = __floats2bfloat162_rn(ra, rb);
    lo = *reinterpret_cast<uint32_t*>(&l);
}

// A fragment image from x (layer 0 only).
__global__ void k_prep0(const float* __restrict__ x, int nmt, int N) {
    int idx = blockIdx.x * blockDim.x + threadIdx.x;
    if (idx >= nmt * 8 * 32) return;
    int l = idx & 31;
    int mk = idx >> 5;
    int ks = mk & 7;
    int mt = mk >> 3;
    int R0 = mt * 16 + (l >> 2);
    int Kl = 2 * (l & 3) + ks * 16;
    uint32_t hi[4], lo[4];
#pragma unroll
    for (int rr = 0; rr < 2; rr++) {
        int row = R0 + 8 * rr;
        bool ok = row < N;
#pragma unroll
        for (int kk = 0; kk < 2; kk++) {
            float2 v = ok ? *(const float2*)(x + (size_t)row * 128 + Kl + 8 * kk)
                          : make_float2(0.f, 0.f);
            split2(v.x, v.y, hi[rr + 2 * kk], lo[rr + 2 * kk]);
        }
    }
    ((uint4*)g_ah)[idx] = make_uint4(hi[0], hi[1], hi[2], hi[3]);
    ((uint4*)g_al)[idx] = make_uint4(lo[0], lo[1], lo[2], lo[3]);
}

// B image for concatenated W2 = [wl; wr] (2*OUT rows x 128 k). NT = OUT/4 tiles.
__global__ void k_wtimg(const float* __restrict__ wl, const float* __restrict__ wr,
                        uint32_t* __restrict__ bh, uint32_t* __restrict__ blo, int OUT) {
    int NT = OUT / 4;
    int idx = blockIdx.x * blockDim.x + threadIdx.x;
    if (idx >= 8 * NT * 32) return;
    int l = idx & 31;
    int kn = idx >> 5;
    int nt = kn % NT;
    int ks = kn / NT;
    int n = nt * 8 + (l >> 2);
    const float* Wrow = (n < OUT) ? (wl + (size_t)n * 128) : (wr + (size_t)(n - OUT) * 128);
#pragma unroll
    for (int r = 0; r < 2; r++) {
        int k = ks * 16 + 2 * (l & 3) + 8 * r;
        uint32_t h, lo2;
        split2(Wrow[k], Wrow[k + 1], h, lo2);
        bh[((ks * NT + nt) * 32 + l) * 2 + r] = h;
        blo[((ks * NT + nt) * 32 + l) * 2 + r] = lo2;
    }
}

__device__ __forceinline__ void mma16816(float* c, const uint4& a, uint32_t b0, uint32_t b1) {
    asm volatile(
        "mma.sync.aligned.m16n8k16.row.col.f32.bf16.bf16.f32 "
        "{%0,%1,%2,%3}, {%4,%5,%6,%7}, {%8,%9}, {%0,%1,%2,%3};"
        : "+f"(c[0]), "+f"(c[1]), "+f"(c[2]), "+f"(c[3])
        : "r"(a.x), "r"(a.y), "r"(a.z), "r"(a.w), "r"(b0), "r"(b1));
}

// Persistent GEMM: [p|q] = h(frag images, K=128) @ [wl;wr]^T.
// 512 thr = 16 warps; warp = (mt-subtile, column half). B staged ONCE per CTA,
// CTA loops over tile-groups (8 mt-tiles each). 3 mma per (ks,nt).
template<int NT>
__global__ __launch_bounds__(512)
void k_mma(const uint32_t* __restrict__ Bh, const uint32_t* __restrict__ Bl,
           unsigned char* __restrict__ pq, int ngrp, int nmt, int N) {
    constexpr int BW = 8 * NT * 64;                // u32 per image
    constexpr int NTH = NT / 2;
    constexpr int OUT = NT * 4;
    constexpr int ROWB = OUT * 6;                  // bytes per pq row
    extern __shared__ uint32_t bs[];
    uint32_t* bsh = bs;
    uint32_t* bsl = bs + BW;

    const int tid = threadIdx.x;
    {
        const uint4* gh = (const uint4*)Bh;
        const uint4* gl = (const uint4*)Bl;
        uint4* s0 = (uint4*)bsh;
        uint4* s1 = (uint4*)bsl;
#pragma unroll
        for (int i = tid; i < BW / 4; i += 512) { s0[i] = gh[i]; s1[i] = gl[i]; }
    }
    __syncthreads();

    const int wid = tid >> 5, lane = tid & 31;
    const int ntb = (wid & 1) * NTH;
    const uint2* sh2 = ((const uint2*)bsh) + lane;
    const uint2* sl2 = ((const uint2*)bsl) + lane;
    const int g = lane >> 2, t = lane & 3;

    for (int grp = blockIdx.x; grp < ngrp; grp += gridDim.x) {
        const int mt = grp * 8 + (wid >> 1);
        if (mt >= nmt) continue;

        float acc[NTH][4];
#pragma unroll
        for (int nt = 0; nt < NTH; nt++)
#pragma unroll
            for (int i = 0; i < 4; i++) acc[nt][i] = 0.f;

        const uint4* pah = ((const uint4*)g_ah) + (size_t)mt * 8 * 32 + lane;
        const uint4* pal = ((const uint4*)g_al) + (size_t)mt * 8 * 32 + lane;

#pragma unroll 1
        for (int ks = 0; ks < 8; ks++) {
            uint4 ah = pah[ks * 32];
            uint4 al = pal[ks * 32];
#pragma unroll
            for (int nt = 0; nt < NTH; nt++) {
                int i2 = (ks * NT + ntb + nt) * 32;
                uint2 wh = sh2[i2];
                uint2 wlo = sl2[i2];
                mma16816(acc[nt], ah, wh.x, wh.y);
                mma16816(acc[nt], ah, wlo.x, wlo.y);
                mma16816(acc[nt], al, wh.x, wh.y);
            }
        }

        const int r0 = mt * 16 + g, r1 = r0 + 8;
        const bool ok0 = r0 < N, ok1 = r1 < N;
#pragma unroll
        for (int nt = 0; nt < NTH; nt++) {
            int col = (ntb + nt) * 8 + 2 * t;
            if (col < OUT) {    // p: fp16 store (uniform per warp)
                if (ok0) *(__half2*)(pq + (size_t)r0 * ROWB + col * 2)
                             = __floats2half2_rn(acc[nt][0], acc[nt][1]);
                if (ok1) *(__half2*)(pq + (size_t)r1 * ROWB + col * 2)
                             = __floats2half2_rn(acc[nt][2], acc[nt][3]);
            } else {            // q: fp32 store
                int qc = col - OUT;
                if (ok0) *(float2*)(pq + (size_t)r0 * ROWB + OUT * 2 + qc * 4)
                             = make_float2(acc[nt][0], acc[nt][1]);
                if (ok1) *(float2*)(pq + (size_t)r1 * ROWB + OUT * 2 + qc * 4)
                             = make_float2(acc[nt][2], acc[nt][3]);
            }
        }
    }
}

// Fused: y = inv*agg(p_fp16) + q + b (+relu/dropout) -> next-layer frag image or out.
// Block = one 16-row tile (512 thr, warp = row).
template<int OUT, bool DROP, bool FRAGS>
__global__ __launch_bounds__(512)
void k_gatherep(const unsigned char* __restrict__ pq, const float* __restrict__ u,
                const float* __restrict__ bias, float* __restrict__ outp, int N) {
    __shared__ float yt[16][132];
    constexpr int ROWB = OUT * 6;
    const int mt = blockIdx.x;
    const int tid = threadIdx.x;
    const int wid = tid >> 5, lane = tid & 31;
    const int r = mt * 16 + wid;
    const bool ok = r < N;

    if (OUT == 128) {
        float4 y = make_float4(0.f, 0.f, 0.f, 0.f);
        if (ok) {
            float4 sA = make_float4(0.f, 0.f, 0.f, 0.f);
            float4 sB = make_float4(0.f, 0.f, 0.f, 0.f);
            int j = g_off[r], j1 = g_off[r + 1];
            for (; j + 3 < j1; j += 4) {
                int s0 = g_csr[j], s1 = g_csr[j + 1], s2 = g_csr[j + 2], s3 = g_csr[j + 3];
                uint2 a = *((const uint2*)(pq + (size_t)s0 * ROWB) + lane);
                uint2 b = *((const uint2*)(pq + (size_t)s1 * ROWB) + lane);
                uint2 c = *((const uint2*)(pq + (size_t)s2 * ROWB) + lane);
                uint2 d = *((const uint2*)(pq + (size_t)s3 * ROWB) + lane);
                float2 a0 = __half22float2(*(__half2*)&a.x), a1 = __half22float2(*(__half2*)&a.y);
                float2 b0 = __half22float2(*(__half2*)&b.x), b1 = __half22float2(*(__half2*)&b.y);
                float2 c0 = __half22float2(*(__half2*)&c.x), c1 = __half22float2(*(__half2*)&c.y);
                float2 d0 = __half22float2(*(__half2*)&d.x), d1 = __half22float2(*(__half2*)&d.y);
                sA.x += a0.x + c0.x; sA.y += a0.y + c0.y; sA.z += a1.x + c1.x; sA.w += a1.y + c1.y;
                sB.x += b0.x + d0.x; sB.y += b0.y + d0.y; sB.z += b1.x + d1.x; sB.w += b1.y + d1.y;
            }
            for (; j < j1; j++) {
                int s0 = g_csr[j];
                uint2 a = *((const uint2*)(pq + (size_t)s0 * ROWB) + lane);
                float2 a0 = __half22float2(*(__half2*)&a.x), a1 = __half22float2(*(__half2*)&a.y);
                sA.x += a0.x; sA.y += a0.y; sA.z += a1.x; sA.w += a1.y;
            }
            float iv = g_inv[r];
            float4 q = ((const float4*)(pq + (size_t)r * ROWB + OUT * 2))[lane];
            float4 b = ((const float4*)bias)[lane];
            y.x = iv * (sA.x + sB.x) + q.x + b.x;
            y.y = iv * (sA.y + sB.y) + q.y + b.y;
            y.z = iv * (sA.z + sB.z) + q.z + b.z;
            y.w = iv * (sA.w + sB.w) + q.w + b.w;
            if (DROP) {
                const float kinv = 1.0f / 0.7f;
                float4 uu = ((const float4*)u)[(size_t)r * 32 + lane];
                y.x = (y.x > 0.f ? y.x : 0.f) * (uu.x >= 0.3f ? kinv : 0.f);
                y.y = (y.y > 0.f ? y.y : 0.f) * (uu.y >= 0.3f ? kinv : 0.f);
                y.z = (y.z > 0.f ? y.z : 0.f) * (uu.z >= 0.3f ? kinv : 0.f);
                y.w = (y.w > 0.f ? y.w : 0.f) * (uu.w >= 0.3f ? kinv : 0.f);
            }
        }
        if (FRAGS) {
            yt[wid][lane * 4 + 0] = y.x;
            yt[wid][lane * 4 + 1] = y.y;
            yt[wid][lane * 4 + 2] = y.z;
            yt[wid][lane * 4 + 3] = y.w;
        } else if (ok) {
            ((float4*)outp)[(size_t)r * 32 + lane] = y;
        }
    } else {  // OUT == 64
        if (ok) {
            float2 sA = make_float2(0.f, 0.f), sB = make_float2(0.f, 0.f);
            int j = g_off[r], j1 = g_off[r + 1];
            for (; j + 3 < j1; j += 4) {
                int s0 = g_csr[j], s1 = g_csr[j + 1], s2 = g_csr[j + 2], s3 = g_csr[j + 3];
                float2 a = __half22float2(*((const __half2*)(pq + (size_t)s0 * ROWB) + lane));
                float2 b = __half22float2(*((const __half2*)(pq + (size_t)s1 * ROWB) + lane));
                float2 c = __half22float2(*((const __half2*)(pq + (size_t)s2 * ROWB) + lane));
                float2 d = __half22float2(*((const __half2*)(pq + (size_t)s3 * ROWB) + lane));
                sA.x += a.x + c.x; sA.y += a.y + c.y;
                sB.x += b.x + d.x; sB.y += b.y + d.y;
            }
            for (; j < j1; j++) {
                float2 a = __half22float2(*((const __half2*)(pq + (size_t)g_csr[j] * ROWB) + lane));
                sA.x += a.x; sA.y += a.y;
            }
            float iv = g_inv[r];
            float2 q = ((const float2*)(pq + (size_t)r * ROWB + OUT * 2))[lane];
            float2 b = ((const float2*)bias)[lane];
            float2 y;
            y.x = iv * (sA.x + sB.x) + q.x + b.x;
            y.y = iv * (sA.y + sB.y) + q.y + b.y;
            ((float2*)outp)[(size_t)r * 32 + lane] = y;
        }
    }

    if (FRAGS) {
        __syncthreads();
        const int base = mt * 1024;
#pragma unroll
        for (int i = tid; i < 1024; i += 512) {
            int ks = i >> 7, l = (i >> 2) & 31, reg = i & 3;
            int gg = (l >> 2) + 8 * (reg & 1);
            int c = 2 * (l & 3) + 16 * ks + 8 * (reg >> 1);
            uint32_t h, lo2;
            split2(yt[gg][c], yt[gg][c + 1], h, lo2);
            g_ah[base + i] = h;
            g_al[base + i] = lo2;
        }
    }
}

extern "C" void kernel_launch(void* const* d_in, const int* in_sizes, int n_in,
                              void* d_out, int out_size) {
    const float* x   = (const float*)d_in[0];
    const float* u1  = (const float*)d_in[1];
    const float* u2  = (const float*)d_in[2];
    const float* wl0 = (const float*)d_in[3];
    const float* bl0 = (const float*)d_in[4];
    const float* wr0 = (const float*)d_in[5];
    const float* wl1 = (const float*)d_in[6];
    const float* bl1 = (const float*)d_in[7];
    const float* wr1 = (const float*)d_in[8];
    const float* wl2 = (const float*)d_in[9];
    const float* bl2 = (const float*)d_in[10];
    const float* wr2 = (const float*)d_in[11];
    const int*   ei  = (const int*)d_in[12];

    const int N = in_sizes[0] / 128;
    const int E = in_sizes[12] / 2;
    const int* src = ei;
    const int* dst = ei + E;
    float* out = (float*)d_out;

    unsigned char* pq;
    uint32_t *bh, *bl;
    cudaGetSymbolAddress((void**)&pq, g_pq);
    cudaGetSymbolAddress((void**)&bh, g_bh);
    cudaGetSymbolAddress((void**)&bl, g_bl);
    const int LS = 8 * 32 * 32 * 2;

    int sms = 148;
    cudaDeviceGetAttribute(&sms, cudaDevAttrMultiProcessorCount, 0);

    const int smem32 = 2 * 8 * 32 * 64 * 4;   // 128 KB
    const int smem16 = 2 * 8 * 16 * 64 * 4;   // 64 KB
    cudaFuncSetAttribute(k_mma<32>, cudaFuncAttributeMaxDynamicSharedMemorySize, smem32);
    cudaFuncSetAttribute(k_mma<16>, cudaFuncAttributeMaxDynamicSharedMemorySize, smem16);

    const int tb = 256;
    const int nmt = (N + 15) / 16;
    const int ngrp = (nmt + 7) / 8;
    const int nsb = (N + 255) / 256;              // scan blocks
    const int gm32 = (sms < ngrp) ? sms : ngrp;
    const int gm16 = (2 * sms < ngrp) ? 2 * sms : ngrp;

    // 1-5: weight images, layer-0 A frags, cnt zero (mma0 is captured launch #6)
    k_wtimg<<<(8 * 32 * 32 + tb - 1) / tb, tb>>>(wl0, wr0, bh + 0 * LS, bl + 0 * LS, 128);
    k_wtimg<<<(8 * 32 * 32 + tb - 1) / tb, tb>>>(wl1, wr1, bh + 1 * LS, bl + 1 * LS, 128);
    k_wtimg<<<(8 * 16 * 32 + tb - 1) / tb, tb>>>(wl2, wr2, bh + 2 * LS, bl + 2 * LS, 64);
    k_prep0<<<(nmt * 8 * 32 + tb - 1) / tb, tb>>>(x, nmt, N);
    k_zero_cnt<<<(N + tb - 1) / tb, tb>>>(N);

    // 6: layer-0 GEMM (profiled)
    k_mma<32><<<gm32, 512, smem32>>>(bh + 0 * LS, bl + 0 * LS, pq, ngrp, nmt, N);

    // 7-11: CSR build (parallel scan)
    k_count<<<(E + tb - 1) / tb, tb>>>(dst, E);
    k_scan1<<<nsb, 256>>>(N);
    k_scan2<<<1, 256>>>(nsb);
    k_scan3<<<nsb, 256>>>(N);
    k_fill<<<(E + tb - 1) / tb, tb>>>(src, dst, E);

    // 12: layer-0 aggregate + epilogue -> h1 frags
    k_gatherep<128, true, true><<<nmt, 512>>>(pq, u1, bl0, nullptr, N);
    // Layer 1
    k_mma<32><<<gm32, 512, smem32>>>(bh + 1 * LS, bl + 1 * LS, pq, ngrp, nmt, N);
    k_gatherep<128, true, true><<<nmt, 512>>>(pq, u2, bl1, nullptr, N);
    // Layer 2
    k_mma<16><<<gm16, 512, smem16>>>(bh + 2 * LS, bl + 2 * LS, pq, ngrp, nmt, N);
    k_gatherep<64, false, false><<<nmt, 512>>>(pq, nullptr, bl2, out, N);
}

// round 14
// speedup vs baseline: 3.3740x; 1.0628x over previous
#include <cuda_runtime.h>
#include <cuda_bf16.h>
#include <cuda_fp16.h>
#include <cstdint>

#define NN 50000
#define EE 800000
#define NMT 3125           // ceil(50000/16)

// ---------------- scratch (__device__ globals; no allocs) ----------------
// pq row layout (per node): p = OUT halves (fp16), then q = OUT floats (fp32).
__device__ __align__(16) unsigned char g_pq[(size_t)NN * 768];
__device__ float g_inv[NN];
__device__ int   g_cnt[NN];
__device__ int   g_off[NN + 1];
__device__ int   g_cur[NN];
__device__ int   g_csr[EE];
__device__ int   g_part[256];
__device__ int   g_poff[256];
// A fragment images (K=128): [mt][ks(8)][lane(32)][4 x b32] bf16x2
__device__ uint32_t g_ah[(size_t)NMT * 8 * 32 * 4];
__device__ uint32_t g_al[(size_t)NMT * 8 * 32 * 4];
// B fragment images: [ks(8)][nt(<=32)][lane(32)][2 x b32]
__device__ uint32_t g_bh[3][8 * 32 * 32 * 2];
__device__ uint32_t g_bl[3][8 * 32 * 32 * 2];

// ---------------- bf16 helpers ----------------
__device__ __forceinline__ void split2(float a, float b, uint32_t& hi, uint32_t& lo) {
    __nv_bfloat162 h = __floats2bfloat162_rn(a, b);
    hi = *reinterpret_cast<uint32_t*>(&h);
    float ra = a - __bfloat162float(h.x);
    float rb = b - __bfloat162float(h.y);
    __nv_bfloat162 l = __floats2bfloat162_rn(ra, rb);
    lo = *reinterpret_cast<uint32_t*>(&l);
}

// ---------------- fused setup: zero cnt + 3x weight images ----------------
__device__ __forceinline__ void wtimg_one(int idx, const float* wl, const float* wr,
                                          uint32_t* bh, uint32_t* blo, int OUT) {
    int NT = OUT / 4;
    int l = idx & 31;
    int kn = idx >> 5;
    int nt = kn % NT;
    int ks = kn / NT;
    int n = nt * 8 + (l >> 2);
    const float* Wrow = (n < OUT) ? (wl + (size_t)n * 128) : (wr + (size_t)(n - OUT) * 128);
#pragma unroll
    for (int r = 0; r < 2; r++) {
        int k = ks * 16 + 2 * (l & 3) + 8 * r;
        uint32_t h, lo2;
        split2(Wrow[k], Wrow[k + 1], h, lo2);
        bh[((ks * NT + nt) * 32 + l) * 2 + r] = h;
        blo[((ks * NT + nt) * 32 + l) * 2 + r] = lo2;
    }
}

__global__ void k_setup(const float* __restrict__ wl0, const float* __restrict__ wr0,
                        const float* __restrict__ wl1, const float* __restrict__ wr1,
                        const float* __restrict__ wl2, const float* __restrict__ wr2,
                        int N) {
    int idx = blockIdx.x * blockDim.x + threadIdx.x;
    if (idx < N) g_cnt[idx] = 0;
    if (idx < 8192) {
        wtimg_one(idx, wl0, wr0, g_bh[0], g_bl[0], 128);
    } else if (idx < 16384) {
        wtimg_one(idx - 8192, wl1, wr1, g_bh[1], g_bl[1], 128);
    } else if (idx < 20480) {
        wtimg_one(idx - 16384, wl2, wr2, g_bh[2], g_bl[2], 64);
    }
}

// ---------------- CSR build ----------------
__global__ void k_count(const int* __restrict__ dst, int E) {
    int e4 = blockIdx.x * blockDim.x + threadIdx.x;
    int e = e4 * 4;
    if (e + 3 < E) {
        int4 d = *(const int4*)(dst + e);
        atomicAdd(&g_cnt[d.x], 1);
        atomicAdd(&g_cnt[d.y], 1);
        atomicAdd(&g_cnt[d.z], 1);
        atomicAdd(&g_cnt[d.w], 1);
    } else {
        for (; e < E; e++) atomicAdd(&g_cnt[dst[e]], 1);
    }
}
// Phase 1: per-block (256 items) partial sums
__global__ void k_scan1(int n) {
    __shared__ int sh[256];
    int t = threadIdx.x;
    int i = blockIdx.x * 256 + t;
    sh[t] = (i < n) ? g_cnt[i] : 0;
    __syncthreads();
    for (int d = 128; d > 0; d >>= 1) {
        if (t < d) sh[t] += sh[t + d];
        __syncthreads();
    }
    if (t == 0) g_part[blockIdx.x] = sh[0];
}
// Phase 2: exclusive scan of partials (1 block, 256 threads)
__global__ void k_scan2(int nb) {
    __shared__ int sh[256];
    int t = threadIdx.x;
    int v = (t < nb) ? g_part[t] : 0;
    sh[t] = v;
    __syncthreads();
    for (int d = 1; d < 256; d <<= 1) {
        int u = (t >= d) ? sh[t - d] : 0;
        __syncthreads();
        sh[t] += u;
        __syncthreads();
    }
    if (t < nb) g_poff[t] = sh[t] - v;
}
// Phase 3: per-block exclusive scan + base; writes off/cur/inv
__global__ void k_scan3(int n) {
    __shared__ int sh[256];
    int t = threadIdx.x;
    int i = blockIdx.x * 256 + t;
    int c = (i < n) ? g_cnt[i] : 0;
    sh[t] = c;
    __syncthreads();
    for (int d = 1; d < 256; d <<= 1) {
        int u = (t >= d) ? sh[t - d] : 0;
        __syncthreads();
        sh[t] += u;
        __syncthreads();
    }
    int base = g_poff[blockIdx.x];
    if (i < n) {
        int excl = base + sh[t] - c;
        g_off[i] = excl;
        g_cur[i] = excl;
        g_inv[i] = 1.0f / (float)max(c, 1);
        if (i == n - 1) g_off[n] = base + sh[t];
    }
}
__global__ void k_fill(const int* __restrict__ src, const int* __restrict__ dst, int E) {
    int e4 = blockIdx.x * blockDim.x + threadIdx.x;
    int e = e4 * 4;
    if (e + 3 < E) {
        int4 d = *(const int4*)(dst + e);
        int4 s = *(const int4*)(src + e);
        g_csr[atomicAdd(&g_cur[d.x], 1)] = s.x;
        g_csr[atomicAdd(&g_cur[d.y], 1)] = s.y;
        g_csr[atomicAdd(&g_cur[d.z], 1)] = s.z;
        g_csr[atomicAdd(&g_cur[d.w], 1)] = s.w;
    } else {
        for (; e < E; e++) g_csr[atomicAdd(&g_cur[dst[e]], 1)] = src[e];
    }
}

// A fragment image from x (layer 0 only).
__global__ void k_prep0(const float* __restrict__ x, int nmt, int N) {
    int idx = blockIdx.x * blockDim.x + threadIdx.x;
    if (idx >= nmt * 8 * 32) return;
    int l = idx & 31;
    int mk = idx >> 5;
    int ks = mk & 7;
    int mt = mk >> 3;
    int R0 = mt * 16 + (l >> 2);
    int Kl = 2 * (l & 3) + ks * 16;
    uint32_t hi[4], lo[4];
#pragma unroll
    for (int rr = 0; rr < 2; rr++) {
        int row = R0 + 8 * rr;
        bool ok = row < N;
#pragma unroll
        for (int kk = 0; kk < 2; kk++) {
            float2 v = ok ? *(const float2*)(x + (size_t)row * 128 + Kl + 8 * kk)
                          : make_float2(0.f, 0.f);
            split2(v.x, v.y, hi[rr + 2 * kk], lo[rr + 2 * kk]);
        }
    }
    ((uint4*)g_ah)[idx] = make_uint4(hi[0], hi[1], hi[2], hi[3]);
    ((uint4*)g_al)[idx] = make_uint4(lo[0], lo[1], lo[2], lo[3]);
}

__device__ __forceinline__ void mma16816(float* c, const uint4& a, uint32_t b0, uint32_t b1) {
    asm volatile(
        "mma.sync.aligned.m16n8k16.row.col.f32.bf16.bf16.f32 "
        "{%0,%1,%2,%3}, {%4,%5,%6,%7}, {%8,%9}, {%0,%1,%2,%3};"
        : "+f"(c[0]), "+f"(c[1]), "+f"(c[2]), "+f"(c[3])
        : "r"(a.x), "r"(a.y), "r"(a.z), "r"(a.w), "r"(b0), "r"(b1));
}

// Persistent GEMM: [p|q] = h(frag images, K=128) @ [wl;wr]^T.
// 512 thr = 16 warps; warp = (2 mt-subtiles, quarter of columns). B staged ONCE
// per CTA and each B fragment feeds TWO A tiles (halved smem traffic).
template<int NT>
__global__ __launch_bounds__(512)
void k_mma(const uint32_t* __restrict__ Bh, const uint32_t* __restrict__ Bl,
           unsigned char* __restrict__ pq, int ngrp, int nmt, int N) {
    constexpr int BW = 8 * NT * 64;                // u32 per image
    constexpr int NTQ = NT / 4;                    // col tiles per warp
    constexpr int OUT = NT * 4;
    constexpr int ROWB = OUT * 6;                  // bytes per pq row
    extern __shared__ uint32_t bs[];
    uint32_t* bsh = bs;
    uint32_t* bsl = bs + BW;

    const int tid = threadIdx.x;
    {
        const uint4* gh = (const uint4*)Bh;
        const uint4* gl = (const uint4*)Bl;
        uint4* s0 = (uint4*)bsh;
        uint4* s1 = (uint4*)bsl;
#pragma unroll
        for (int i = tid; i < BW / 4; i += 512) { s0[i] = gh[i]; s1[i] = gl[i]; }
    }
    __syncthreads();

    const int wid = tid >> 5, lane = tid & 31;
    const int wrow = wid & 3;                      // 2 mt-tiles each
    const int qcol = wid >> 2;                     // column quarter
    const int ntb = qcol * NTQ;
    const uint2* sh2 = ((const uint2*)bsh) + lane;
    const uint2* sl2 = ((const uint2*)bsl) + lane;
    const int g = lane >> 2, t = lane & 3;
    const uint4 z4 = make_uint4(0, 0, 0, 0);

    for (int grp = blockIdx.x; grp < ngrp; grp += gridDim.x) {
        const int mt0 = grp * 8 + wrow * 2;
        const int mt1 = mt0 + 1;
        const bool v0 = mt0 < nmt, v1 = mt1 < nmt;
        if (!v0) continue;

        float acc[2][NTQ][4];
#pragma unroll
        for (int m = 0; m < 2; m++)
#pragma unroll
            for (int nt = 0; nt < NTQ; nt++)
#pragma unroll
                for (int i = 0; i < 4; i++) acc[m][nt][i] = 0.f;

        const uint4* pah0 = ((const uint4*)g_ah) + (size_t)mt0 * 8 * 32 + lane;
        const uint4* pal0 = ((const uint4*)g_al) + (size_t)mt0 * 8 * 32 + lane;
        const uint4* pah1 = ((const uint4*)g_ah) + (size_t)mt1 * 8 * 32 + lane;
        const uint4* pal1 = ((const uint4*)g_al) + (size_t)mt1 * 8 * 32 + lane;

#pragma unroll 1
        for (int ks = 0; ks < 8; ks++) {
            uint4 ah0 = pah0[ks * 32];
            uint4 al0 = pal0[ks * 32];
            uint4 ah1 = v1 ? pah1[ks * 32] : z4;
            uint4 al1 = v1 ? pal1[ks * 32] : z4;
#pragma unroll
            for (int nt = 0; nt < NTQ; nt++) {
                int i2 = (ks * NT + ntb + nt) * 32;
                uint2 wh = sh2[i2];
                uint2 wlo = sl2[i2];
                mma16816(acc[0][nt], ah0, wh.x, wh.y);
                mma16816(acc[0][nt], ah0, wlo.x, wlo.y);
                mma16816(acc[0][nt], al0, wh.x, wh.y);
                mma16816(acc[1][nt], ah1, wh.x, wh.y);
                mma16816(acc[1][nt], ah1, wlo.x, wlo.y);
                mma16816(acc[1][nt], al1, wh.x, wh.y);
            }
        }

#pragma unroll
        for (int m = 0; m < 2; m++) {
            const int mt = m ? mt1 : mt0;
            if (m && !v1) break;
            const int r0 = mt * 16 + g, r1 = r0 + 8;
            const bool ok0 = r0 < N, ok1 = r1 < N;
#pragma unroll
            for (int nt = 0; nt < NTQ; nt++) {
                int col = (ntb + nt) * 8 + 2 * t;
                if (col < OUT) {    // p: fp16 (uniform per warp quarter)
                    if (ok0) *(__half2*)(pq + (size_t)r0 * ROWB + col * 2)
                                 = __floats2half2_rn(acc[m][nt][0], acc[m][nt][1]);
                    if (ok1) *(__half2*)(pq + (size_t)r1 * ROWB + col * 2)
                                 = __floats2half2_rn(acc[m][nt][2], acc[m][nt][3]);
                } else {            // q: fp32
                    int qc = col - OUT;
                    if (ok0) *(float2*)(pq + (size_t)r0 * ROWB + OUT * 2 + qc * 4)
                                 = make_float2(acc[m][nt][0], acc[m][nt][1]);
                    if (ok1) *(float2*)(pq + (size_t)r1 * ROWB + OUT * 2 + qc * 4)
                                 = make_float2(acc[m][nt][2], acc[m][nt][3]);
                }
            }
        }
    }
}

// Fused: y = inv*agg(p_fp16) + q + b (+relu/dropout) -> next-layer frag image or out.
template<int OUT, bool DROP, bool FRAGS>
__global__ __launch_bounds__(512)
void k_gatherep(const unsigned char* __restrict__ pq, const float* __restrict__ u,
                const float* __restrict__ bias, float* __restrict__ outp, int N) {
    __shared__ float yt[16][132];
    constexpr int ROWB = OUT * 6;
    const int mt = blockIdx.x;
    const int tid = threadIdx.x;
    const int wid = tid >> 5, lane = tid & 31;
    const int r = mt * 16 + wid;
    const bool ok = r < N;

    if (OUT == 128) {
        float4 y = make_float4(0.f, 0.f, 0.f, 0.f);
        if (ok) {
            float4 sA = make_float4(0.f, 0.f, 0.f, 0.f);
            float4 sB = make_float4(0.f, 0.f, 0.f, 0.f);
            int j = g_off[r], j1 = g_off[r + 1];
            for (; j + 3 < j1; j += 4) {
                int s0 = g_csr[j], s1 = g_csr[j + 1], s2 = g_csr[j + 2], s3 = g_csr[j + 3];
                uint2 a = *((const uint2*)(pq + (size_t)s0 * ROWB) + lane);
                uint2 b = *((const uint2*)(pq + (size_t)s1 * ROWB) + lane);
                uint2 c = *((const uint2*)(pq + (size_t)s2 * ROWB) + lane);
                uint2 d = *((const uint2*)(pq + (size_t)s3 * ROWB) + lane);
                float2 a0 = __half22float2(*(__half2*)&a.x), a1 = __half22float2(*(__half2*)&a.y);
                float2 b0 = __half22float2(*(__half2*)&b.x), b1 = __half22float2(*(__half2*)&b.y);
                float2 c0 = __half22float2(*(__half2*)&c.x), c1 = __half22float2(*(__half2*)&c.y);
                float2 d0 = __half22float2(*(__half2*)&d.x), d1 = __half22float2(*(__half2*)&d.y);
                sA.x += a0.x + c0.x; sA.y += a0.y + c0.y; sA.z += a1.x + c1.x; sA.w += a1.y + c1.y;
                sB.x += b0.x + d0.x; sB.y += b0.y + d0.y; sB.z += b1.x + d1.x; sB.w += b1.y + d1.y;
            }
            for (; j < j1; j++) {
                int s0 = g_csr[j];
                uint2 a = *((const uint2*)(pq + (size_t)s0 * ROWB) + lane);
                float2 a0 = __half22float2(*(__half2*)&a.x), a1 = __half22float2(*(__half2*)&a.y);
                sA.x += a0.x; sA.y += a0.y; sA.z += a1.x; sA.w += a1.y;
            }
            float iv = g_inv[r];
            float4 q = ((const float4*)(pq + (size_t)r * ROWB + OUT * 2))[lane];
            float4 b = ((const float4*)bias)[lane];
            y.x = iv * (sA.x + sB.x) + q.x + b.x;
            y.y = iv * (sA.y + sB.y) + q.y + b.y;
            y.z = iv * (sA.z + sB.z) + q.z + b.z;
            y.w = iv * (sA.w + sB.w) + q.w + b.w;
            if (DROP) {
                const float kinv = 1.0f / 0.7f;
                float4 uu = ((const float4*)u)[(size_t)r * 32 + lane];
                y.x = (y.x > 0.f ? y.x : 0.f) * (uu.x >= 0.3f ? kinv : 0.f);
                y.y = (y.y > 0.f ? y.y : 0.f) * (uu.y >= 0.3f ? kinv : 0.f);
                y.z = (y.z > 0.f ? y.z : 0.f) * (uu.z >= 0.3f ? kinv : 0.f);
                y.w = (y.w > 0.f ? y.w : 0.f) * (uu.w >= 0.3f ? kinv : 0.f);
            }
        }
        if (FRAGS) {
            yt[wid][lane * 4 + 0] = y.x;
            yt[wid][lane * 4 + 1] = y.y;
            yt[wid][lane * 4 + 2] = y.z;
            yt[wid][lane * 4 + 3] = y.w;
        } else if (ok) {
            ((float4*)outp)[(size_t)r * 32 + lane] = y;
        }
    } else {  // OUT == 64
        if (ok) {
            float2 sA = make_float2(0.f, 0.f), sB = make_float2(0.f, 0.f);
            int j = g_off[r], j1 = g_off[r + 1];
            for (; j + 3 < j1; j += 4) {
                int s0 = g_csr[j], s1 = g_csr[j + 1], s2 = g_csr[j + 2], s3 = g_csr[j + 3];
                float2 a = __half22float2(*((const __half2*)(pq + (size_t)s0 * ROWB) + lane));
                float2 b = __half22float2(*((const __half2*)(pq + (size_t)s1 * ROWB) + lane));
                float2 c = __half22float2(*((const __half2*)(pq + (size_t)s2 * ROWB) + lane));
                float2 d = __half22float2(*((const __half2*)(pq + (size_t)s3 * ROWB) + lane));
                sA.x += a.x + c.x; sA.y += a.y + c.y;
                sB.x += b.x + d.x; sB.y += b.y + d.y;
            }
            for (; j < j1; j++) {
                float2 a = __half22float2(*((const __half2*)(pq + (size_t)g_csr[j] * ROWB) + lane));
                sA.x += a.x; sA.y += a.y;
            }
            float iv = g_inv[r];
            float2 q = ((const float2*)(pq + (size_t)r * ROWB + OUT * 2))[lane];
            float2 b = ((const float2*)bias)[lane];
            float2 y;
            y.x = iv * (sA.x + sB.x) + q.x + b.x;
            y.y = iv * (sA.y + sB.y) + q.y + b.y;
            ((float2*)outp)[(size_t)r * 32 + lane] = y;
        }
    }

    if (FRAGS) {
        __syncthreads();
        const int base = mt * 1024;
#pragma unroll
        for (int i = tid; i < 1024; i += 512) {
            int ks = i >> 7, l = (i >> 2) & 31, reg = i & 3;
            int gg = (l >> 2) + 8 * (reg & 1);
            int c = 2 * (l & 3) + 16 * ks + 8 * (reg >> 1);
            uint32_t h, lo2;
            split2(yt[gg][c], yt[gg][c + 1], h, lo2);
            g_ah[base + i] = h;
            g_al[base + i] = lo2;
        }
    }
}

extern "C" void kernel_launch(void* const* d_in, const int* in_sizes, int n_in,
                              void* d_out, int out_size) {
    const float* x   = (const float*)d_in[0];
    const float* u1  = (const float*)d_in[1];
    const float* u2  = (const float*)d_in[2];
    const float* wl0 = (const float*)d_in[3];
    const float* bl0 = (const float*)d_in[4];
    const float* wr0 = (const float*)d_in[5];
    const float* wl1 = (const float*)d_in[6];
    const float* bl1 = (const float*)d_in[7];
    const float* wr1 = (const float*)d_in[8];
    const float* wl2 = (const float*)d_in[9];
    const float* bl2 = (const float*)d_in[10];
    const float* wr2 = (const float*)d_in[11];
    const int*   ei  = (const int*)d_in[12];

    const int N = in_sizes[0] / 128;
    const int E = in_sizes[12] / 2;
    const int* src = ei;
    const int* dst = ei + E;
    float* out = (float*)d_out;

    unsigned char* pq;
    uint32_t *bh, *bl;
    cudaGetSymbolAddress((void**)&pq, g_pq);
    cudaGetSymbolAddress((void**)&bh, g_bh);
    cudaGetSymbolAddress((void**)&bl, g_bl);
    const int LS = 8 * 32 * 32 * 2;

    int sms = 148;
    cudaDeviceGetAttribute(&sms, cudaDevAttrMultiProcessorCount, 0);

    const int smem32 = 2 * 8 * 32 * 64 * 4;   // 128 KB
    const int smem16 = 2 * 8 * 16 * 64 * 4;   // 64 KB
    cudaFuncSetAttribute(k_mma<32>, cudaFuncAttributeMaxDynamicSharedMemorySize, smem32);
    cudaFuncSetAttribute(k_mma<16>, cudaFuncAttributeMaxDynamicSharedMemorySize, smem16);

    const int tb = 256;
    const int nmt = (N + 15) / 16;
    const int ngrp = (nmt + 7) / 8;
    const int nsb = (N + 255) / 256;
    const int gm32 = (sms < ngrp) ? sms : ngrp;
    const int gm16 = (2 * sms < ngrp) ? 2 * sms : ngrp;
    const int e4b = (E / 4 + tb) / tb + 1;

    // 1: setup (zero cnt + weight images), 2: layer-0 A frags
    k_setup<<<(N + tb - 1) / tb, tb>>>(wl0, wr0, wl1, wr1, wl2, wr2, N);
    k_prep0<<<(nmt * 8 * 32 + tb - 1) / tb, tb>>>(x, nmt, N);
    // 3-5: CSR count + scan (independent of mma0)
    k_count<<<e4b, tb>>>(dst, E);
    k_scan1<<<nsb, 256>>>(N);
    k_scan2<<<1, 256>>>(nsb);
    // 6: layer-0 GEMM (profiled launch)
    k_mma<32><<<gm32, 512, smem32>>>(bh + 0 * LS, bl + 0 * LS, pq, ngrp, nmt, N);
    // 7-8: finish CSR
    k_scan3<<<nsb, 256>>>(N);
    k_fill<<<e4b, tb>>>(src, dst, E);
    // 9: layer-0 aggregate + epilogue -> h1 frags
    k_gatherep<128, true, true><<<nmt, 512>>>(pq, u1, bl0, nullptr, N);
    // Layer 1
    k_mma<32><<<gm32, 512, smem32>>>(bh + 1 * LS, bl + 1 * LS, pq, ngrp, nmt, N);
    k_gatherep<128, true, true><<<nmt, 512>>>(pq, u2, bl1, nullptr, N);
    // Layer 2
    k_mma<16><<<gm16, 512, smem16>>>(bh + 2 * LS, bl + 2 * LS, pq, ngrp, nmt, N);
    k_gatherep<64, false, false><<<nmt, 512>>>(pq, nullptr, bl2, out, N);
}

// round 15
// speedup vs baseline: 3.4736x; 1.0295x over previous
#include <cuda_runtime.h>
#include <cuda_bf16.h>
#include <cuda_fp16.h>
#include <cstdint>

#define NN 50000
#define EE 800000
#define NMT 3125           // ceil(50000/16)

// ---------------- scratch (__device__ globals; no allocs) ----------------
// pq row layout (per node): p = OUT halves (fp16), then q = OUT floats (fp32).
__device__ __align__(16) unsigned char g_pq[(size_t)NN * 768];
__device__ float g_inv[NN];
__device__ int   g_cnt[NN];
__device__ int   g_off[NN + 1];
__device__ int   g_cur[NN];
__device__ int   g_csr[EE];
__device__ int   g_work;                     // fill work-stealing ticket
__device__ volatile int g_blkagg[256];       // scan lookback: block aggregates
__device__ volatile int g_blkpre[256];       // inclusive prefixes
__device__ volatile int g_blkst[256];        // 0=none 1=agg 2=prefix
// A fragment images (K=128): [mt][ks(8)][lane(32)][4 x b32] bf16x2
__device__ uint32_t g_ah[(size_t)NMT * 8 * 32 * 4];
__device__ uint32_t g_al[(size_t)NMT * 8 * 32 * 4];
// B fragment images: [ks(8)][nt(<=32)][lane(32)][2 x b32]
__device__ uint32_t g_bh[3][8 * 32 * 32 * 2];
__device__ uint32_t g_bl[3][8 * 32 * 32 * 2];

// ---------------- bf16 helpers ----------------
__device__ __forceinline__ void split2(float a, float b, uint32_t& hi, uint32_t& lo) {
    __nv_bfloat162 h = __floats2bfloat162_rn(a, b);
    hi = *reinterpret_cast<uint32_t*>(&h);
    float ra = a - __bfloat162float(h.x);
    float rb = b - __bfloat162float(h.y);
    __nv_bfloat162 l = __floats2bfloat162_rn(ra, rb);
    lo = *reinterpret_cast<uint32_t*>(&l);
}

// ---------------- setup: zero cnt/flags + 3x weight images ----------------
__device__ __forceinline__ void wtimg_one(int idx, const float* wl, const float* wr,
                                          uint32_t* bh, uint32_t* blo, int OUT) {
    int NT = OUT / 4;
    int l = idx & 31;
    int kn = idx >> 5;
    int nt = kn % NT;
    int ks = kn / NT;
    int n = nt * 8 + (l >> 2);
    const float* Wrow = (n < OUT) ? (wl + (size_t)n * 128) : (wr + (size_t)(n - OUT) * 128);
#pragma unroll
    for (int r = 0; r < 2; r++) {
        int k = ks * 16 + 2 * (l & 3) + 8 * r;
        uint32_t h, lo2;
        split2(Wrow[k], Wrow[k + 1], h, lo2);
        bh[((ks * NT + nt) * 32 + l) * 2 + r] = h;
        blo[((ks * NT + nt) * 32 + l) * 2 + r] = lo2;
    }
}

__global__ void k_setup(const float* __restrict__ wl0, const float* __restrict__ wr0,
                        const float* __restrict__ wl1, const float* __restrict__ wr1,
                        const float* __restrict__ wl2, const float* __restrict__ wr2,
                        int N) {
    int idx = blockIdx.x * blockDim.x + threadIdx.x;
    if (idx < N) g_cnt[idx] = 0;
    if (idx < 256) g_blkst[idx] = 0;
    if (idx == 0) g_work = 0;
    if (idx < 8192) {
        wtimg_one(idx, wl0, wr0, g_bh[0], g_bl[0], 128);
    } else if (idx < 16384) {
        wtimg_one(idx - 8192, wl1, wr1, g_bh[1], g_bl[1], 128);
    } else if (idx < 20480) {
        wtimg_one(idx - 16384, wl2, wr2, g_bh[2], g_bl[2], 64);
    }
}

// ---------------- fused: layer-0 A fragment image + edge count ----------------
__global__ void k_prep_count(const float* __restrict__ x, const int* __restrict__ dst,
                             int prepBlocks, int nmt, int N, int E) {
    const int b = blockIdx.x;
    const int t = threadIdx.x;
    if (b < prepBlocks) {
        int idx = b * 256 + t;
        if (idx >= nmt * 8 * 32) return;
        int l = idx & 31;
        int mk = idx >> 5;
        int ks = mk & 7;
        int mt = mk >> 3;
        int R0 = mt * 16 + (l >> 2);
        int Kl = 2 * (l & 3) + ks * 16;
        uint32_t hi[4], lo[4];
#pragma unroll
        for (int rr = 0; rr < 2; rr++) {
            int row = R0 + 8 * rr;
            bool ok = row < N;
#pragma unroll
            for (int kk = 0; kk < 2; kk++) {
                float2 v = ok ? *(const float2*)(x + (size_t)row * 128 + Kl + 8 * kk)
                              : make_float2(0.f, 0.f);
                split2(v.x, v.y, hi[rr + 2 * kk], lo[rr + 2 * kk]);
            }
        }
        ((uint4*)g_ah)[idx] = make_uint4(hi[0], hi[1], hi[2], hi[3]);
        ((uint4*)g_al)[idx] = make_uint4(lo[0], lo[1], lo[2], lo[3]);
    } else {
        int e = ((b - prepBlocks) * 256 + t) * 4;
        if (e + 3 < E) {
            int4 d = *(const int4*)(dst + e);
            atomicAdd(&g_cnt[d.x], 1);
            atomicAdd(&g_cnt[d.y], 1);
            atomicAdd(&g_cnt[d.z], 1);
            atomicAdd(&g_cnt[d.w], 1);
        } else {
            for (; e < E; e++) atomicAdd(&g_cnt[dst[e]], 1);
        }
    }
}

// ---------------- single-kernel scan (decoupled lookback) ----------------
__global__ void k_scanlb(int n) {
    __shared__ int sh[256];
    __shared__ int s_base;
    const int b = blockIdx.x;
    const int t = threadIdx.x;
    const int i = b * 256 + t;
    const int c = (i < n) ? g_cnt[i] : 0;
    sh[t] = c;
    __syncthreads();
    for (int d = 1; d < 256; d <<= 1) {
        int u = (t >= d) ? sh[t - d] : 0;
        __syncthreads();
        sh[t] += u;
        __syncthreads();
    }
    const int agg = sh[255];
    if (t == 0) {
        if (b == 0) {
            g_blkpre[0] = agg;
            __threadfence();
            g_blkst[0] = 2;
            s_base = 0;
        } else {
            g_blkagg[b] = agg;
            __threadfence();
            g_blkst[b] = 1;
        }
    }
    if (b > 0 && t < 32) {        // warp-parallel lookback (warp 0)
        const int lane = t;
        int run = 0;
        int j = b - 1;
        while (true) {
            int idx = j - lane;
            int st;
            do { st = (idx >= 0) ? g_blkst[idx] : 2; }
            while (__any_sync(0xFFFFFFFFu, st == 0));
            unsigned m = __ballot_sync(0xFFFFFFFFu, st == 2);
            int L = (m == 0) ? 32 : (__ffs(m) - 1);
            int val = 0;
            if (idx >= 0 && lane <= L) {
                val = (lane == L) ? g_blkpre[idx] : g_blkagg[idx];
            }
#pragma unroll
            for (int o = 16; o > 0; o >>= 1) val += __shfl_xor_sync(0xFFFFFFFFu, val, o);
            run += val;
            if (m) break;
            j -= 32;
        }
        if (lane == 0) {
            g_blkpre[b] = run + agg;
            __threadfence();
            g_blkst[b] = 2;
            s_base = run;
        }
    }
    __syncthreads();
    const int base = s_base;
    if (i < n) {
        int excl = base + sh[t] - c;
        g_off[i] = excl;
        g_cur[i] = excl;
        g_inv[i] = 1.0f / (float)max(c, 1);
        if (i == n - 1) g_off[n] = base + sh[t];
    }
}

__device__ __forceinline__ void mma16816(float* c, const uint4& a, uint32_t b0, uint32_t b1) {
    asm volatile(
        "mma.sync.aligned.m16n8k16.row.col.f32.bf16.bf16.f32 "
        "{%0,%1,%2,%3}, {%4,%5,%6,%7}, {%8,%9}, {%0,%1,%2,%3};"
        : "+f"(c[0]), "+f"(c[1]), "+f"(c[2]), "+f"(c[3])
        : "r"(a.x), "r"(a.y), "r"(a.z), "r"(a.w), "r"(b0), "r"(b1));
}

// Persistent GEMM: [p|q] = h(frag images, K=128) @ [wl;wr]^T.
// 512 thr = 16 warps; warp = (2 mt-subtiles, quarter of columns). B staged ONCE.
// FILL variant: after GEMM groups, CTAs steal 2048-edge tiles and build g_csr.
template<int NT, bool FILL>
__global__ __launch_bounds__(512)
void k_mma(const uint32_t* __restrict__ Bh, const uint32_t* __restrict__ Bl,
           unsigned char* __restrict__ pq, int ngrp, int nmt, int N,
           const int* __restrict__ src, const int* __restrict__ dst, int E) {
    constexpr int BW = 8 * NT * 64;                // u32 per image
    constexpr int NTQ = NT / 4;                    // col tiles per warp
    constexpr int OUT = NT * 4;
    constexpr int ROWB = OUT * 6;                  // bytes per pq row
    extern __shared__ uint32_t bs[];
    uint32_t* bsh = bs;
    uint32_t* bsl = bs + BW;

    const int tid = threadIdx.x;
    {
        const uint4* gh = (const uint4*)Bh;
        const uint4* gl = (const uint4*)Bl;
        uint4* s0 = (uint4*)bsh;
        uint4* s1 = (uint4*)bsl;
#pragma unroll
        for (int i = tid; i < BW / 4; i += 512) { s0[i] = gh[i]; s1[i] = gl[i]; }
    }
    __syncthreads();

    const int wid = tid >> 5, lane = tid & 31;
    const int wrow = wid & 3;                      // 2 mt-tiles each
    const int qcol = wid >> 2;                     // column quarter
    const int ntb = qcol * NTQ;
    const uint2* sh2 = ((const uint2*)bsh) + lane;
    const uint2* sl2 = ((const uint2*)bsl) + lane;
    const int g = lane >> 2, t = lane & 3;
    const uint4 z4 = make_uint4(0, 0, 0, 0);

    for (int grp = blockIdx.x; grp < ngrp; grp += gridDim.x) {
        const int mt0 = grp * 8 + wrow * 2;
        const int mt1 = mt0 + 1;
        const bool v0 = mt0 < nmt, v1 = mt1 < nmt;
        if (!v0) continue;

        float acc[2][NTQ][4];
#pragma unroll
        for (int m = 0; m < 2; m++)
#pragma unroll
            for (int nt = 0; nt < NTQ; nt++)
#pragma unroll
                for (int i = 0; i < 4; i++) acc[m][nt][i] = 0.f;

        const uint4* pah0 = ((const uint4*)g_ah) + (size_t)mt0 * 8 * 32 + lane;
        const uint4* pal0 = ((const uint4*)g_al) + (size_t)mt0 * 8 * 32 + lane;
        const uint4* pah1 = ((const uint4*)g_ah) + (size_t)mt1 * 8 * 32 + lane;
        const uint4* pal1 = ((const uint4*)g_al) + (size_t)mt1 * 8 * 32 + lane;

#pragma unroll 1
        for (int ks = 0; ks < 8; ks++) {
            uint4 ah0 = pah0[ks * 32];
            uint4 al0 = pal0[ks * 32];
            uint4 ah1 = v1 ? pah1[ks * 32] : z4;
            uint4 al1 = v1 ? pal1[ks * 32] : z4;
#pragma unroll
            for (int nt = 0; nt < NTQ; nt++) {
                int i2 = (ks * NT + ntb + nt) * 32;
                uint2 wh = sh2[i2];
                uint2 wlo = sl2[i2];
                mma16816(acc[0][nt], ah0, wh.x, wh.y);
                mma16816(acc[0][nt], ah0, wlo.x, wlo.y);
                mma16816(acc[0][nt], al0, wh.x, wh.y);
                mma16816(acc[1][nt], ah1, wh.x, wh.y);
                mma16816(acc[1][nt], ah1, wlo.x, wlo.y);
                mma16816(acc[1][nt], al1, wh.x, wh.y);
            }
        }

#pragma unroll
        for (int m = 0; m < 2; m++) {
            const int mt = m ? mt1 : mt0;
            if (m && !v1) break;
            const int r0 = mt * 16 + g, r1 = r0 + 8;
            const bool ok0 = r0 < N, ok1 = r1 < N;
#pragma unroll
            for (int nt = 0; nt < NTQ; nt++) {
                int col = (ntb + nt) * 8 + 2 * t;
                if (col < OUT) {    // p: fp16 (uniform per warp quarter)
                    if (ok0) *(__half2*)(pq + (size_t)r0 * ROWB + col * 2)
                                 = __floats2half2_rn(acc[m][nt][0], acc[m][nt][1]);
                    if (ok1) *(__half2*)(pq + (size_t)r1 * ROWB + col * 2)
                                 = __floats2half2_rn(acc[m][nt][2], acc[m][nt][3]);
                } else {            // q: fp32
                    int qc = col - OUT;
                    if (ok0) *(float2*)(pq + (size_t)r0 * ROWB + OUT * 2 + qc * 4)
                                 = make_float2(acc[m][nt][0], acc[m][nt][1]);
                    if (ok1) *(float2*)(pq + (size_t)r1 * ROWB + OUT * 2 + qc * 4)
                                 = make_float2(acc[m][nt][2], acc[m][nt][3]);
                }
            }
        }
    }

    if (FILL) {   // work-stealing CSR fill tail (g_cur ready from k_scanlb)
        __shared__ int s_tile;
        const int ntile = (E + 2047) / 2048;
        while (true) {
            if (tid == 0) s_tile = atomicAdd(&g_work, 1);
            __syncthreads();
            const int tile = s_tile;
            __syncthreads();
            if (tile >= ntile) break;
            int e = tile * 2048 + tid * 4;
            if (e + 3 < E) {
                int4 d = *(const int4*)(dst + e);
                int4 s = *(const int4*)(src + e);
                g_csr[atomicAdd(&g_cur[d.x], 1)] = s.x;
                g_csr[atomicAdd(&g_cur[d.y], 1)] = s.y;
                g_csr[atomicAdd(&g_cur[d.z], 1)] = s.z;
                g_csr[atomicAdd(&g_cur[d.w], 1)] = s.w;
            } else {
                for (; e < E; e++) g_csr[atomicAdd(&g_cur[dst[e]], 1)] = src[e];
            }
        }
    }
}

// Fused: y = inv*agg(p_fp16) + q + b (+relu/dropout) -> next-layer frag image or out.
template<int OUT, bool DROP, bool FRAGS>
__global__ __launch_bounds__(512)
void k_gatherep(const unsigned char* __restrict__ pq, const float* __restrict__ u,
                const float* __restrict__ bias, float* __restrict__ outp, int N) {
    __shared__ float yt[16][132];
    constexpr int ROWB = OUT * 6;
    const int mt = blockIdx.x;
    const int tid = threadIdx.x;
    const int wid = tid >> 5, lane = tid & 31;
    const int r = mt * 16 + wid;
    const bool ok = r < N;

    if (OUT == 128) {
        float4 y = make_float4(0.f, 0.f, 0.f, 0.f);
        if (ok) {
            float4 sA = make_float4(0.f, 0.f, 0.f, 0.f);
            float4 sB = make_float4(0.f, 0.f, 0.f, 0.f);
            int j = g_off[r], j1 = g_off[r + 1];
            for (; j + 3 < j1; j += 4) {
                int s0 = g_csr[j], s1 = g_csr[j + 1], s2 = g_csr[j + 2], s3 = g_csr[j + 3];
                uint2 a = *((const uint2*)(pq + (size_t)s0 * ROWB) + lane);
                uint2 b = *((const uint2*)(pq + (size_t)s1 * ROWB) + lane);
                uint2 c = *((const uint2*)(pq + (size_t)s2 * ROWB) + lane);
                uint2 d = *((const uint2*)(pq + (size_t)s3 * ROWB) + lane);
                float2 a0 = __half22float2(*(__half2*)&a.x), a1 = __half22float2(*(__half2*)&a.y);
                float2 b0 = __half22float2(*(__half2*)&b.x), b1 = __half22float2(*(__half2*)&b.y);
                float2 c0 = __half22float2(*(__half2*)&c.x), c1 = __half22float2(*(__half2*)&c.y);
                float2 d0 = __half22float2(*(__half2*)&d.x), d1 = __half22float2(*(__half2*)&d.y);
                sA.x += a0.x + c0.x; sA.y += a0.y + c0.y; sA.z += a1.x + c1.x; sA.w += a1.y + c1.y;
                sB.x += b0.x + d0.x; sB.y += b0.y + d0.y; sB.z += b1.x + d1.x; sB.w += b1.y + d1.y;
            }
            for (; j < j1; j++) {
                int s0 = g_csr[j];
                uint2 a = *((const uint2*)(pq + (size_t)s0 * ROWB) + lane);
                float2 a0 = __half22float2(*(__half2*)&a.x), a1 = __half22float2(*(__half2*)&a.y);
                sA.x += a0.x; sA.y += a0.y; sA.z += a1.x; sA.w += a1.y;
            }
            float iv = g_inv[r];
            float4 q = ((const float4*)(pq + (size_t)r * ROWB + OUT * 2))[lane];
            float4 b = ((const float4*)bias)[lane];
            y.x = iv * (sA.x + sB.x) + q.x + b.x;
            y.y = iv * (sA.y + sB.y) + q.y + b.y;
            y.z = iv * (sA.z + sB.z) + q.z + b.z;
            y.w = iv * (sA.w + sB.w) + q.w + b.w;
            if (DROP) {
                const float kinv = 1.0f / 0.7f;
                float4 uu = ((const float4*)u)[(size_t)r * 32 + lane];
                y.x = (y.x > 0.f ? y.x : 0.f) * (uu.x >= 0.3f ? kinv : 0.f);
                y.y = (y.y > 0.f ? y.y : 0.f) * (uu.y >= 0.3f ? kinv : 0.f);
                y.z = (y.z > 0.f ? y.z : 0.f) * (uu.z >= 0.3f ? kinv : 0.f);
                y.w = (y.w > 0.f ? y.w : 0.f) * (uu.w >= 0.3f ? kinv : 0.f);
            }
        }
        if (FRAGS) {
            yt[wid][lane * 4 + 0] = y.x;
            yt[wid][lane * 4 + 1] = y.y;
            yt[wid][lane * 4 + 2] = y.z;
            yt[wid][lane * 4 + 3] = y.w;
        } else if (ok) {
            ((float4*)outp)[(size_t)r * 32 + lane] = y;
        }
    } else {  // OUT == 64
        if (ok) {
            float2 sA = make_float2(0.f, 0.f), sB = make_float2(0.f, 0.f);
            int j = g_off[r], j1 = g_off[r + 1];
            for (; j + 3 < j1; j += 4) {
                int s0 = g_csr[j], s1 = g_csr[j + 1], s2 = g_csr[j + 2], s3 = g_csr[j + 3];
                float2 a = __half22float2(*((const __half2*)(pq + (size_t)s0 * ROWB) + lane));
                float2 b = __half22float2(*((const __half2*)(pq + (size_t)s1 * ROWB) + lane));
                float2 c = __half22float2(*((const __half2*)(pq + (size_t)s2 * ROWB) + lane));
                float2 d = __half22float2(*((const __half2*)(pq + (size_t)s3 * ROWB) + lane));
                sA.x += a.x + c.x; sA.y += a.y + c.y;
                sB.x += b.x + d.x; sB.y += b.y + d.y;
            }
            for (; j < j1; j++) {
                float2 a = __half22float2(*((const __half2*)(pq + (size_t)g_csr[j] * ROWB) + lane));
                sA.x += a.x; sA.y += a.y;
            }
            float iv = g_inv[r];
            float2 q = ((const float2*)(pq + (size_t)r * ROWB + OUT * 2))[lane];
            float2 b = ((const float2*)bias)[lane];
            float2 y;
            y.x = iv * (sA.x + sB.x) + q.x + b.x;
            y.y = iv * (sA.y + sB.y) + q.y + b.y;
            ((float2*)outp)[(size_t)r * 32 + lane] = y;
        }
    }

    if (FRAGS) {
        __syncthreads();
        const int base = mt * 1024;
#pragma unroll
        for (int i = tid; i < 1024; i += 512) {
            int ks = i >> 7, l = (i >> 2) & 31, reg = i & 3;
            int gg = (l >> 2) + 8 * (reg & 1);
            int c = 2 * (l & 3) + 16 * ks + 8 * (reg >> 1);
            uint32_t h, lo2;
            split2(yt[gg][c], yt[gg][c + 1], h, lo2);
            g_ah[base + i] = h;
            g_al[base + i] = lo2;
        }
    }
}

extern "C" void kernel_launch(void* const* d_in, const int* in_sizes, int n_in,
                              void* d_out, int out_size) {
    const float* x   = (const float*)d_in[0];
    const float* u1  = (const float*)d_in[1];
    const float* u2  = (const float*)d_in[2];
    const float* wl0 = (const float*)d_in[3];
    const float* bl0 = (const float*)d_in[4];
    const float* wr0 = (const float*)d_in[5];
    const float* wl1 = (const float*)d_in[6];
    const float* bl1 = (const float*)d_in[7];
    const float* wr1 = (const float*)d_in[8];
    const float* wl2 = (const float*)d_in[9];
    const float* bl2 = (const float*)d_in[10];
    const float* wr2 = (const float*)d_in[11];
    const int*   ei  = (const int*)d_in[12];

    const int N = in_sizes[0] / 128;
    const int E = in_sizes[12] / 2;
    const int* src = ei;
    const int* dst = ei + E;
    float* out = (float*)d_out;

    unsigned char* pq;
    uint32_t *bh, *bl;
    cudaGetSymbolAddress((void**)&pq, g_pq);
    cudaGetSymbolAddress((void**)&bh, g_bh);
    cudaGetSymbolAddress((void**)&bl, g_bl);
    const int LS = 8 * 32 * 32 * 2;

    int sms = 148;
    cudaDeviceGetAttribute(&sms, cudaDevAttrMultiProcessorCount, 0);

    const int smem32 = 2 * 8 * 32 * 64 * 4;   // 128 KB
    const int smem16 = 2 * 8 * 16 * 64 * 4;   // 64 KB
    cudaFuncSetAttribute(k_mma<32, true>, cudaFuncAttributeMaxDynamicSharedMemorySize, smem32);
    cudaFuncSetAttribute(k_mma<32, false>, cudaFuncAttributeMaxDynamicSharedMemorySize, smem32);
    cudaFuncSetAttribute(k_mma<16, false>, cudaFuncAttributeMaxDynamicSharedMemorySize, smem16);

    const int tb = 256;
    const int nmt = (N + 15) / 16;
    const int ngrp = (nmt + 7) / 8;
    const int nsb = (N + 255) / 256;
    const int gm32 = (sms < ngrp) ? sms : ngrp;
    const int gm16 = (2 * sms < ngrp) ? 2 * sms : ngrp;
    const int prepB = (nmt * 8 * 32 + tb - 1) / tb;
    const int cntB = (E / 4 + tb) / tb + 1;

    // 1: setup (zero cnt/flags + weight images)
    k_setup<<<(N + tb - 1) / tb, tb>>>(wl0, wr0, wl1, wr1, wl2, wr2, N);
    // 2: layer-0 A frags + edge count (fused, disjoint block ranges)
    k_prep_count<<<prepB + cntB, tb>>>(x, dst, prepB, nmt, N, E);
    // 3: CSR offsets (single-kernel decoupled-lookback scan)
    k_scanlb<<<nsb, 256>>>(N);
    // 4: layer-0 GEMM + work-stealing CSR fill tail
    k_mma<32, true><<<gm32, 512, smem32>>>(bh + 0 * LS, bl + 0 * LS, pq, ngrp, nmt, N, src, dst, E);
    // 5: layer-0 aggregate + epilogue -> h1 frags
    k_gatherep<128, true, true><<<nmt, 512>>>(pq, u1, bl0, nullptr, N);
    // 6-7: layer 1
    k_mma<32, false><<<gm32, 512, smem32>>>(bh + 1 * LS, bl + 1 * LS, pq, ngrp, nmt, N, src, dst, E);
    k_gatherep<128, true, true><<<nmt, 512>>>(pq, u2, bl1, nullptr, N);
    // 8-9: layer 2
    k_mma<16, false><<<gm16, 512, smem16>>>(bh + 2 * LS, bl + 2 * LS, pq, ngrp, nmt, N, src, dst, E);
    k_gatherep<64, false, false><<<nmt, 512>>>(pq, nullptr, bl2, out, N);
}

// round 16
// speedup vs baseline: 3.4936x; 1.0058x over previous
#include <cuda_runtime.h>
#include <cuda_bf16.h>
#include <cuda_fp16.h>
#include <cstdint>

#define NN 50000
#define EE 800000
#define NMT 3125           // ceil(50000/16)

// ---------------- scratch (__device__ globals; no allocs) ----------------
// pq row layout (per node): p = OUT halves (fp16), then q = OUT floats (fp32).
__device__ __align__(16) unsigned char g_pq[(size_t)NN * 768];
__device__ float g_inv[NN];
__device__ int   g_cnt[NN];
__device__ int   g_off[NN + 1];
__device__ int   g_cur[NN];
__device__ int   g_csr[EE];
__device__ int   g_work;                     // fill work-stealing ticket
__device__ volatile int g_blkagg[256];       // scan lookback: block aggregates
__device__ volatile int g_blkpre[256];       // inclusive prefixes
__device__ volatile int g_blkst[256];        // 0=none 1=agg 2=prefix
// A fragment images (K=128): [mt][ks(8)][lane(32)][4 x b32] bf16x2
__device__ uint32_t g_ah[(size_t)NMT * 8 * 32 * 4];
__device__ uint32_t g_al[(size_t)NMT * 8 * 32 * 4];
// B fragment images: [ks(8)][nt(<=32)][lane(32)][2 x b32]
__device__ uint32_t g_bh[3][8 * 32 * 32 * 2];
__device__ uint32_t g_bl[3][8 * 32 * 32 * 2];

// ---------------- bf16 helpers ----------------
__device__ __forceinline__ void split2(float a, float b, uint32_t& hi, uint32_t& lo) {
    __nv_bfloat162 h = __floats2bfloat162_rn(a, b);
    hi = *reinterpret_cast<uint32_t*>(&h);
    float ra = a - __bfloat162float(h.x);
    float rb = b - __bfloat162float(h.y);
    __nv_bfloat162 l = __floats2bfloat162_rn(ra, rb);
    lo = *reinterpret_cast<uint32_t*>(&l);
}

// ---------------- setup: zero cnt/flags + 3x weight images ----------------
__device__ __forceinline__ void wtimg_one(int idx, const float* wl, const float* wr,
                                          uint32_t* bh, uint32_t* blo, int OUT) {
    int NT = OUT / 4;
    int l = idx & 31;
    int kn = idx >> 5;
    int nt = kn % NT;
    int ks = kn / NT;
    int n = nt * 8 + (l >> 2);
    const float* Wrow = (n < OUT) ? (wl + (size_t)n * 128) : (wr + (size_t)(n - OUT) * 128);
#pragma unroll
    for (int r = 0; r < 2; r++) {
        int k = ks * 16 + 2 * (l & 3) + 8 * r;
        uint32_t h, lo2;
        split2(Wrow[k], Wrow[k + 1], h, lo2);
        bh[((ks * NT + nt) * 32 + l) * 2 + r] = h;
        blo[((ks * NT + nt) * 32 + l) * 2 + r] = lo2;
    }
}

__global__ void k_setup(const float* __restrict__ wl0, const float* __restrict__ wr0,
                        const float* __restrict__ wl1, const float* __restrict__ wr1,
                        const float* __restrict__ wl2, const float* __restrict__ wr2,
                        int N) {
    int idx = blockIdx.x * blockDim.x + threadIdx.x;
    if (idx < N) g_cnt[idx] = 0;
    if (idx < 256) g_blkst[idx] = 0;
    if (idx == 0) g_work = 0;
    if (idx < 8192) {
        wtimg_one(idx, wl0, wr0, g_bh[0], g_bl[0], 128);
    } else if (idx < 16384) {
        wtimg_one(idx - 8192, wl1, wr1, g_bh[1], g_bl[1], 128);
    } else if (idx < 20480) {
        wtimg_one(idx - 16384, wl2, wr2, g_bh[2], g_bl[2], 64);
    }
}

// ---------------- fused: layer-0 A fragment image + edge count ----------------
__global__ void k_prep_count(const float* __restrict__ x, const int* __restrict__ dst,
                             int prepBlocks, int nmt, int N, int E) {
    const int b = blockIdx.x;
    const int t = threadIdx.x;
    if (b < prepBlocks) {
        int idx = b * 256 + t;
        if (idx >= nmt * 8 * 32) return;
        int l = idx & 31;
        int mk = idx >> 5;
        int ks = mk & 7;
        int mt = mk >> 3;
        int R0 = mt * 16 + (l >> 2);
        int Kl = 2 * (l & 3) + ks * 16;
        uint32_t hi[4], lo[4];
#pragma unroll
        for (int rr = 0; rr < 2; rr++) {
            int row = R0 + 8 * rr;
            bool ok = row < N;
#pragma unroll
            for (int kk = 0; kk < 2; kk++) {
                float2 v = ok ? *(const float2*)(x + (size_t)row * 128 + Kl + 8 * kk)
                              : make_float2(0.f, 0.f);
                split2(v.x, v.y, hi[rr + 2 * kk], lo[rr + 2 * kk]);
            }
        }
        ((uint4*)g_ah)[idx] = make_uint4(hi[0], hi[1], hi[2], hi[3]);
        ((uint4*)g_al)[idx] = make_uint4(lo[0], lo[1], lo[2], lo[3]);
    } else {
        int e = ((b - prepBlocks) * 256 + t) * 4;
        if (e + 3 < E) {
            int4 d = *(const int4*)(dst + e);
            atomicAdd(&g_cnt[d.x], 1);
            atomicAdd(&g_cnt[d.y], 1);
            atomicAdd(&g_cnt[d.z], 1);
            atomicAdd(&g_cnt[d.w], 1);
        } else {
            for (; e < E; e++) atomicAdd(&g_cnt[dst[e]], 1);
        }
    }
}

// ---------------- single-kernel scan (decoupled lookback) ----------------
__global__ void k_scanlb(int n) {
    __shared__ int sh[256];
    __shared__ int s_base;
    const int b = blockIdx.x;
    const int t = threadIdx.x;
    const int i = b * 256 + t;
    const int c = (i < n) ? g_cnt[i] : 0;
    sh[t] = c;
    __syncthreads();
    for (int d = 1; d < 256; d <<= 1) {
        int u = (t >= d) ? sh[t - d] : 0;
        __syncthreads();
        sh[t] += u;
        __syncthreads();
    }
    const int agg = sh[255];
    if (t == 0) {
        if (b == 0) {
            g_blkpre[0] = agg;
            __threadfence();
            g_blkst[0] = 2;
            s_base = 0;
        } else {
            g_blkagg[b] = agg;
            __threadfence();
            g_blkst[b] = 1;
        }
    }
    if (b > 0 && t < 32) {        // warp-parallel lookback (warp 0)
        const int lane = t;
        int run = 0;
        int j = b - 1;
        while (true) {
            int idx = j - lane;
            int st;
            do { st = (idx >= 0) ? g_blkst[idx] : 2; }
            while (__any_sync(0xFFFFFFFFu, st == 0));
            unsigned m = __ballot_sync(0xFFFFFFFFu, st == 2);
            int L = (m == 0) ? 32 : (__ffs(m) - 1);
            int val = 0;
            if (idx >= 0 && lane <= L) {
                val = (lane == L) ? g_blkpre[idx] : g_blkagg[idx];
            }
#pragma unroll
            for (int o = 16; o > 0; o >>= 1) val += __shfl_xor_sync(0xFFFFFFFFu, val, o);
            run += val;
            if (m) break;
            j -= 32;
        }
        if (lane == 0) {
            g_blkpre[b] = run + agg;
            __threadfence();
            g_blkst[b] = 2;
            s_base = run;
        }
    }
    __syncthreads();
    const int base = s_base;
    if (i < n) {
        int excl = base + sh[t] - c;
        g_off[i] = excl;
        g_cur[i] = excl;
        g_inv[i] = 1.0f / (float)max(c, 1);
        if (i == n - 1) g_off[n] = base + sh[t];
    }
}

__device__ __forceinline__ void mma16816(float* c, const uint4& a, uint32_t b0, uint32_t b1) {
    asm volatile(
        "mma.sync.aligned.m16n8k16.row.col.f32.bf16.bf16.f32 "
        "{%0,%1,%2,%3}, {%4,%5,%6,%7}, {%8,%9}, {%0,%1,%2,%3};"
        : "+f"(c[0]), "+f"(c[1]), "+f"(c[2]), "+f"(c[3])
        : "r"(a.x), "r"(a.y), "r"(a.z), "r"(a.w), "r"(b0), "r"(b1));
}

// One 2048-edge CSR fill tile (work-stealing). Returns false when exhausted.
__device__ __forceinline__ bool fill_tile(const int* __restrict__ src,
                                          const int* __restrict__ dst, int E,
                                          int tid, int* s_tile) {
    const int ntile = (E + 2047) / 2048;
    if (tid == 0) *s_tile = atomicAdd(&g_work, 1);
    __syncthreads();
    const int tile = *s_tile;
    __syncthreads();
    if (tile >= ntile) return false;
    int e = tile * 2048 + tid * 4;
    if (e + 3 < E) {
        int4 d = *(const int4*)(dst + e);
        int4 s = *(const int4*)(src + e);
        g_csr[atomicAdd(&g_cur[d.x], 1)] = s.x;
        g_csr[atomicAdd(&g_cur[d.y], 1)] = s.y;
        g_csr[atomicAdd(&g_cur[d.z], 1)] = s.z;
        g_csr[atomicAdd(&g_cur[d.w], 1)] = s.w;
    } else {
        for (; e < E; e++) g_csr[atomicAdd(&g_cur[dst[e]], 1)] = src[e];
    }
    return true;
}

// Persistent GEMM: [p|q] = h(frag images, K=128) @ [wl;wr]^T.
// 512 thr = 16 warps; warp = (2 mt-subtiles, quarter of columns). B staged ONCE.
// FILL: one CSR fill tile is interleaved after each GEMM group (overlaps the
// L2-atomic fill with tensor work), remainder drained in a tail loop.
template<int NT, bool FILL>
__global__ __launch_bounds__(512)
void k_mma(const uint32_t* __restrict__ Bh, const uint32_t* __restrict__ Bl,
           unsigned char* __restrict__ pq, int ngrp, int nmt, int N,
           const int* __restrict__ src, const int* __restrict__ dst, int E) {
    constexpr int BW = 8 * NT * 64;                // u32 per image
    constexpr int NTQ = NT / 4;                    // col tiles per warp
    constexpr int OUT = NT * 4;
    constexpr int ROWB = OUT * 6;                  // bytes per pq row
    extern __shared__ uint32_t bs[];
    uint32_t* bsh = bs;
    uint32_t* bsl = bs + BW;
    __shared__ int s_tile;

    const int tid = threadIdx.x;
    {
        const uint4* gh = (const uint4*)Bh;
        const uint4* gl = (const uint4*)Bl;
        uint4* s0 = (uint4*)bsh;
        uint4* s1 = (uint4*)bsl;
#pragma unroll
        for (int i = tid; i < BW / 4; i += 512) { s0[i] = gh[i]; s1[i] = gl[i]; }
    }
    __syncthreads();

    const int wid = tid >> 5, lane = tid & 31;
    const int wrow = wid & 3;                      // 2 mt-tiles each
    const int qcol = wid >> 2;                     // column quarter
    const int ntb = qcol * NTQ;
    const uint2* sh2 = ((const uint2*)bsh) + lane;
    const uint2* sl2 = ((const uint2*)bsl) + lane;
    const int g = lane >> 2, t = lane & 3;
    const uint4 z4 = make_uint4(0, 0, 0, 0);
    bool more_fill = FILL;

    for (int grp = blockIdx.x; grp < ngrp; grp += gridDim.x) {
        const int mt0 = grp * 8 + wrow * 2;
        const int mt1 = mt0 + 1;
        const bool v0 = mt0 < nmt, v1 = mt1 < nmt;

        if (v0) {
            float acc[2][NTQ][4];
#pragma unroll
            for (int m = 0; m < 2; m++)
#pragma unroll
                for (int nt = 0; nt < NTQ; nt++)
#pragma unroll
                    for (int i = 0; i < 4; i++) acc[m][nt][i] = 0.f;

            const uint4* pah0 = ((const uint4*)g_ah) + (size_t)mt0 * 8 * 32 + lane;
            const uint4* pal0 = ((const uint4*)g_al) + (size_t)mt0 * 8 * 32 + lane;
            const uint4* pah1 = ((const uint4*)g_ah) + (size_t)mt1 * 8 * 32 + lane;
            const uint4* pal1 = ((const uint4*)g_al) + (size_t)mt1 * 8 * 32 + lane;

#pragma unroll 2
            for (int ks = 0; ks < 8; ks++) {
                uint4 ah0 = pah0[ks * 32];
                uint4 al0 = pal0[ks * 32];
                uint4 ah1 = v1 ? pah1[ks * 32] : z4;
                uint4 al1 = v1 ? pal1[ks * 32] : z4;
#pragma unroll
                for (int nt = 0; nt < NTQ; nt++) {
                    int i2 = (ks * NT + ntb + nt) * 32;
                    uint2 wh = sh2[i2];
                    uint2 wlo = sl2[i2];
                    mma16816(acc[0][nt], ah0, wh.x, wh.y);
                    mma16816(acc[0][nt], ah0, wlo.x, wlo.y);
                    mma16816(acc[0][nt], al0, wh.x, wh.y);
                    mma16816(acc[1][nt], ah1, wh.x, wh.y);
                    mma16816(acc[1][nt], ah1, wlo.x, wlo.y);
                    mma16816(acc[1][nt], al1, wh.x, wh.y);
                }
            }

#pragma unroll
            for (int m = 0; m < 2; m++) {
                const int mt = m ? mt1 : mt0;
                if (m && !v1) break;
                const int r0 = mt * 16 + g, r1 = r0 + 8;
                const bool ok0 = r0 < N, ok1 = r1 < N;
#pragma unroll
                for (int nt = 0; nt < NTQ; nt++) {
                    int col = (ntb + nt) * 8 + 2 * t;
                    if (col < OUT) {    // p: fp16 (uniform per warp quarter)
                        if (ok0) *(__half2*)(pq + (size_t)r0 * ROWB + col * 2)
                                     = __floats2half2_rn(acc[m][nt][0], acc[m][nt][1]);
                        if (ok1) *(__half2*)(pq + (size_t)r1 * ROWB + col * 2)
                                     = __floats2half2_rn(acc[m][nt][2], acc[m][nt][3]);
                    } else {            // q: fp32
                        int qc = col - OUT;
                        if (ok0) *(float2*)(pq + (size_t)r0 * ROWB + OUT * 2 + qc * 4)
                                     = make_float2(acc[m][nt][0], acc[m][nt][1]);
                        if (ok1) *(float2*)(pq + (size_t)r1 * ROWB + OUT * 2 + qc * 4)
                                     = make_float2(acc[m][nt][2], acc[m][nt][3]);
                    }
                }
            }
        }

        if (FILL && more_fill) {   // overlap one fill tile per group
            more_fill = fill_tile(src, dst, E, tid, &s_tile);
        }
    }

    if (FILL) {                    // drain remaining fill tiles
        while (more_fill) more_fill = fill_tile(src, dst, E, tid, &s_tile);
    }
}

// Fused: y = inv*agg(p_fp16) + q + b (+relu/dropout) -> next-layer frag image or out.
template<int OUT, bool DROP, bool FRAGS>
__global__ __launch_bounds__(512)
void k_gatherep(const unsigned char* __restrict__ pq, const float* __restrict__ u,
                const float* __restrict__ bias, float* __restrict__ outp, int N) {
    __shared__ float yt[16][132];
    constexpr int ROWB = OUT * 6;
    const int mt = blockIdx.x;
    const int tid = threadIdx.x;
    const int wid = tid >> 5, lane = tid & 31;
    const int r = mt * 16 + wid;
    const bool ok = r < N;

    if (OUT == 128) {
        float4 y = make_float4(0.f, 0.f, 0.f, 0.f);
        if (ok) {
            float4 sA = make_float4(0.f, 0.f, 0.f, 0.f);
            float4 sB = make_float4(0.f, 0.f, 0.f, 0.f);
            int j = g_off[r], j1 = g_off[r + 1];
            for (; j + 3 < j1; j += 4) {
                int s0 = g_csr[j], s1 = g_csr[j + 1], s2 = g_csr[j + 2], s3 = g_csr[j + 3];
                uint2 a = *((const uint2*)(pq + (size_t)s0 * ROWB) + lane);
                uint2 b = *((const uint2*)(pq + (size_t)s1 * ROWB) + lane);
                uint2 c = *((const uint2*)(pq + (size_t)s2 * ROWB) + lane);
                uint2 d = *((const uint2*)(pq + (size_t)s3 * ROWB) + lane);
                float2 a0 = __half22float2(*(__half2*)&a.x), a1 = __half22float2(*(__half2*)&a.y);
                float2 b0 = __half22float2(*(__half2*)&b.x), b1 = __half22float2(*(__half2*)&b.y);
                float2 c0 = __half22float2(*(__half2*)&c.x), c1 = __half22float2(*(__half2*)&c.y);
                float2 d0 = __half22float2(*(__half2*)&d.x), d1 = __half22float2(*(__half2*)&d.y);
                sA.x += a0.x + c0.x; sA.y += a0.y + c0.y; sA.z += a1.x + c1.x; sA.w += a1.y + c1.y;
                sB.x += b0.x + d0.x; sB.y += b0.y + d0.y; sB.z += b1.x + d1.x; sB.w += b1.y + d1.y;
            }
            for (; j < j1; j++) {
                int s0 = g_csr[j];
                uint2 a = *((const uint2*)(pq + (size_t)s0 * ROWB) + lane);
                float2 a0 = __half22float2(*(__half2*)&a.x), a1 = __half22float2(*(__half2*)&a.y);
                sA.x += a0.x; sA.y += a0.y; sA.z += a1.x; sA.w += a1.y;
            }
            float iv = g_inv[r];
            float4 q = ((const float4*)(pq + (size_t)r * ROWB + OUT * 2))[lane];
            float4 b = ((const float4*)bias)[lane];
            y.x = iv * (sA.x + sB.x) + q.x + b.x;
            y.y = iv * (sA.y + sB.y) + q.y + b.y;
            y.z = iv * (sA.z + sB.z) + q.z + b.z;
            y.w = iv * (sA.w + sB.w) + q.w + b.w;
            if (DROP) {
                const float kinv = 1.0f / 0.7f;
                float4 uu = ((const float4*)u)[(size_t)r * 32 + lane];
                y.x = (y.x > 0.f ? y.x : 0.f) * (uu.x >= 0.3f ? kinv : 0.f);
                y.y = (y.y > 0.f ? y.y : 0.f) * (uu.y >= 0.3f ? kinv : 0.f);
                y.z = (y.z > 0.f ? y.z : 0.f) * (uu.z >= 0.3f ? kinv : 0.f);
                y.w = (y.w > 0.f ? y.w : 0.f) * (uu.w >= 0.3f ? kinv : 0.f);
            }
        }
        if (FRAGS) {
            yt[wid][lane * 4 + 0] = y.x;
            yt[wid][lane * 4 + 1] = y.y;
            yt[wid][lane * 4 + 2] = y.z;
            yt[wid][lane * 4 + 3] = y.w;
        } else if (ok) {
            ((float4*)outp)[(size_t)r * 32 + lane] = y;
        }
    } else {  // OUT == 64
        if (ok) {
            float2 sA = make_float2(0.f, 0.f), sB = make_float2(0.f, 0.f);
            int j = g_off[r], j1 = g_off[r + 1];
            for (; j + 3 < j1; j += 4) {
                int s0 = g_csr[j], s1 = g_csr[j + 1], s2 = g_csr[j + 2], s3 = g_csr[j + 3];
                float2 a = __half22float2(*((const __half2*)(pq + (size_t)s0 * ROWB) + lane));
                float2 b = __half22float2(*((const __half2*)(pq + (size_t)s1 * ROWB) + lane));
                float2 c = __half22float2(*((const __half2*)(pq + (size_t)s2 * ROWB) + lane));
                float2 d = __half22float2(*((const __half2*)(pq + (size_t)s3 * ROWB) + lane));
                sA.x += a.x + c.x; sA.y += a.y + c.y;
                sB.x += b.x + d.x; sB.y += b.y + d.y;
            }
            for (; j < j1; j++) {
                float2 a = __half22float2(*((const __half2*)(pq + (size_t)g_csr[j] * ROWB) + lane));
                sA.x += a.x; sA.y += a.y;
            }
            float iv = g_inv[r];
            float2 q = ((const float2*)(pq + (size_t)r * ROWB + OUT * 2))[lane];
            float2 b = ((const float2*)bias)[lane];
            float2 y;
            y.x = iv * (sA.x + sB.x) + q.x + b.x;
            y.y = iv * (sA.y + sB.y) + q.y + b.y;
            ((float2*)outp)[(size_t)r * 32 + lane] = y;
        }
    }

    if (FRAGS) {
        __syncthreads();
        const int base = mt * 1024;
#pragma unroll
        for (int i = tid; i < 1024; i += 512) {
            int ks = i >> 7, l = (i >> 2) & 31, reg = i & 3;
            int gg = (l >> 2) + 8 * (reg & 1);
            int c = 2 * (l & 3) + 16 * ks + 8 * (reg >> 1);
            uint32_t h, lo2;
            split2(yt[gg][c], yt[gg][c + 1], h, lo2);
            g_ah[base + i] = h;
            g_al[base + i] = lo2;
        }
    }
}

extern "C" void kernel_launch(void* const* d_in, const int* in_sizes, int n_in,
                              void* d_out, int out_size) {
    const float* x   = (const float*)d_in[0];
    const float* u1  = (const float*)d_in[1];
    const float* u2  = (const float*)d_in[2];
    const float* wl0 = (const float*)d_in[3];
    const float* bl0 = (const float*)d_in[4];
    const float* wr0 = (const float*)d_in[5];
    const float* wl1 = (const float*)d_in[6];
    const float* bl1 = (const float*)d_in[7];
    const float* wr1 = (const float*)d_in[8];
    const float* wl2 = (const float*)d_in[9];
    const float* bl2 = (const float*)d_in[10];
    const float* wr2 = (const float*)d_in[11];
    const int*   ei  = (const int*)d_in[12];

    const int N = in_sizes[0] / 128;
    const int E = in_sizes[12] / 2;
    const int* src = ei;
    const int* dst = ei + E;
    float* out = (float*)d_out;

    unsigned char* pq;
    uint32_t *bh, *bl;
    cudaGetSymbolAddress((void**)&pq, g_pq);
    cudaGetSymbolAddress((void**)&bh, g_bh);
    cudaGetSymbolAddress((void**)&bl, g_bl);
    const int LS = 8 * 32 * 32 * 2;

    int sms = 148;
    cudaDeviceGetAttribute(&sms, cudaDevAttrMultiProcessorCount, 0);

    const int smem32 = 2 * 8 * 32 * 64 * 4;   // 128 KB
    const int smem16 = 2 * 8 * 16 * 64 * 4;   // 64 KB
    cudaFuncSetAttribute(k_mma<32, true>, cudaFuncAttributeMaxDynamicSharedMemorySize, smem32);
    cudaFuncSetAttribute(k_mma<32, false>, cudaFuncAttributeMaxDynamicSharedMemorySize, smem32);
    cudaFuncSetAttribute(k_mma<16, false>, cudaFuncAttributeMaxDynamicSharedMemorySize, smem16);

    const int tb = 256;
    const int nmt = (N + 15) / 16;
    const int ngrp = (nmt + 7) / 8;
    const int nsb = (N + 255) / 256;
    const int gm32 = (sms < ngrp) ? sms : ngrp;
    const int gm16 = (2 * sms < ngrp) ? 2 * sms : ngrp;
    const int prepB = (nmt * 8 * 32 + tb - 1) / tb;
    const int cntB = (E / 4 + tb) / tb + 1;

    // 1: setup (zero cnt/flags + weight images)
    k_setup<<<(N + tb - 1) / tb, tb>>>(wl0, wr0, wl1, wr1, wl2, wr2, N);
    // 2: layer-0 A frags + edge count (fused, disjoint block ranges)
    k_prep_count<<<prepB + cntB, tb>>>(x, dst, prepB, nmt, N, E);
    // 3: CSR offsets (single-kernel decoupled-lookback scan)
    k_scanlb<<<nsb, 256>>>(N);
    // 4: layer-0 GEMM with interleaved CSR fill
    k_mma<32, true><<<gm32, 512, smem32>>>(bh + 0 * LS, bl + 0 * LS, pq, ngrp, nmt, N, src, dst, E);
    // 5: layer-0 aggregate + epilogue -> h1 frags
    k_gatherep<128, true, true><<<nmt, 512>>>(pq, u1, bl0, nullptr, N);
    // 6-7: layer 1
    k_mma<32, false><<<gm32, 512, smem32>>>(bh + 1 * LS, bl + 1 * LS, pq, ngrp, nmt, N, src, dst, E);
    k_gatherep<128, true, true><<<nmt, 512>>>(pq, u2, bl1, nullptr, N);
    // 8-9: layer 2
    k_mma<16, false><<<gm16, 512, smem16>>>(bh + 2 * LS, bl + 2 * LS, pq, ngrp, nmt, N, src, dst, E);
    k_gatherep<64, false, false><<<nmt, 512>>>(pq, nullptr, bl2, out, N);
}

// round 17
// speedup vs baseline: 3.5199x; 1.0075x over previous
#include <cuda_runtime.h>
#include <cuda_bf16.h>
#include <cuda_fp16.h>
#include <cstdint>

#define NN 50000
#define EE 800000
#define NMT 3125           // ceil(50000/16)

// ---------------- scratch (__device__ globals; no allocs) ----------------
// pq row layout (per node): p = OUT halves (fp16), then q = OUT floats (fp32).
__device__ __align__(16) unsigned char g_pq[(size_t)NN * 768];
__device__ float g_inv[NN];
__device__ int   g_cnt[NN];
__device__ int   g_off[NN + 1];
__device__ int   g_cur[NN];
__device__ int   g_csr[EE];
__device__ int   g_work;                     // fill work-stealing ticket
__device__ volatile int g_blkagg[256];       // scan lookback: block aggregates
__device__ volatile int g_blkpre[256];       // inclusive prefixes
__device__ volatile int g_blkst[256];        // 0=none 1=agg 2=prefix
// A fragment images (K=128): [mt][ks(8)][lane(32)][4 x b32] bf16x2
__device__ uint32_t g_ah[(size_t)NMT * 8 * 32 * 4];
__device__ uint32_t g_al[(size_t)NMT * 8 * 32 * 4];
// B fragment images: [ks(8)][nt(<=32)][lane(32)][2 x b32]
__device__ uint32_t g_bh[3][8 * 32 * 32 * 2];
__device__ uint32_t g_bl[3][8 * 32 * 32 * 2];

// ---------------- bf16 helpers ----------------
__device__ __forceinline__ void split2(float a, float b, uint32_t& hi, uint32_t& lo) {
    __nv_bfloat162 h = __floats2bfloat162_rn(a, b);
    hi = *reinterpret_cast<uint32_t*>(&h);
    float ra = a - __bfloat162float(h.x);
    float rb = b - __bfloat162float(h.y);
    __nv_bfloat162 l = __floats2bfloat162_rn(ra, rb);
    lo = *reinterpret_cast<uint32_t*>(&l);
}

// ---------------- setup: zero cnt/flags + 3x weight images ----------------
__device__ __forceinline__ void wtimg_one(int idx, const float* wl, const float* wr,
                                          uint32_t* bh, uint32_t* blo, int OUT) {
    int NT = OUT / 4;
    int l = idx & 31;
    int kn = idx >> 5;
    int nt = kn % NT;
    int ks = kn / NT;
    int n = nt * 8 + (l >> 2);
    const float* Wrow = (n < OUT) ? (wl + (size_t)n * 128) : (wr + (size_t)(n - OUT) * 128);
#pragma unroll
    for (int r = 0; r < 2; r++) {
        int k = ks * 16 + 2 * (l & 3) + 8 * r;
        uint32_t h, lo2;
        split2(Wrow[k], Wrow[k + 1], h, lo2);
        bh[((ks * NT + nt) * 32 + l) * 2 + r] = h;
        blo[((ks * NT + nt) * 32 + l) * 2 + r] = lo2;
    }
}

__global__ void k_setup(const float* __restrict__ wl0, const float* __restrict__ wr0,
                        const float* __restrict__ wl1, const float* __restrict__ wr1,
                        const float* __restrict__ wl2, const float* __restrict__ wr2,
                        int N) {
    int idx = blockIdx.x * blockDim.x + threadIdx.x;
    if (idx < N) g_cnt[idx] = 0;
    if (idx < 256) g_blkst[idx] = 0;
    if (idx == 0) g_work = 0;
    if (idx < 8192) {
        wtimg_one(idx, wl0, wr0, g_bh[0], g_bl[0], 128);
    } else if (idx < 16384) {
        wtimg_one(idx - 8192, wl1, wr1, g_bh[1], g_bl[1], 128);
    } else if (idx < 20480) {
        wtimg_one(idx - 16384, wl2, wr2, g_bh[2], g_bl[2], 64);
    }
}

// ---------------- fused: layer-0 A fragment image + edge count ----------------
__global__ void k_prep_count(const float* __restrict__ x, const int* __restrict__ dst,
                             int prepBlocks, int nmt, int N, int E) {
    const int b = blockIdx.x;
    const int t = threadIdx.x;
    if (b < prepBlocks) {
        int idx = b * 256 + t;
        if (idx >= nmt * 8 * 32) return;
        int l = idx & 31;
        int mk = idx >> 5;
        int ks = mk & 7;
        int mt = mk >> 3;
        int R0 = mt * 16 + (l >> 2);
        int Kl = 2 * (l & 3) + ks * 16;
        uint32_t hi[4], lo[4];
#pragma unroll
        for (int rr = 0; rr < 2; rr++) {
            int row = R0 + 8 * rr;
            bool ok = row < N;
#pragma unroll
            for (int kk = 0; kk < 2; kk++) {
                float2 v = ok ? *(const float2*)(x + (size_t)row * 128 + Kl + 8 * kk)
                              : make_float2(0.f, 0.f);
                split2(v.x, v.y, hi[rr + 2 * kk], lo[rr + 2 * kk]);
            }
        }
        ((uint4*)g_ah)[idx] = make_uint4(hi[0], hi[1], hi[2], hi[3]);
        ((uint4*)g_al)[idx] = make_uint4(lo[0], lo[1], lo[2], lo[3]);
    } else {
        int e = ((b - prepBlocks) * 256 + t) * 4;
        if (e + 3 < E) {
            int4 d = *(const int4*)(dst + e);
            atomicAdd(&g_cnt[d.x], 1);
            atomicAdd(&g_cnt[d.y], 1);
            atomicAdd(&g_cnt[d.z], 1);
            atomicAdd(&g_cnt[d.w], 1);
        } else {
            for (; e < E; e++) atomicAdd(&g_cnt[dst[e]], 1);
        }
    }
}

// ---------------- single-kernel scan (decoupled lookback) ----------------
__global__ void k_scanlb(int n) {
    __shared__ int sh[256];
    __shared__ int s_base;
    const int b = blockIdx.x;
    const int t = threadIdx.x;
    const int i = b * 256 + t;
    const int c = (i < n) ? g_cnt[i] : 0;
    sh[t] = c;
    __syncthreads();
    for (int d = 1; d < 256; d <<= 1) {
        int u = (t >= d) ? sh[t - d] : 0;
        __syncthreads();
        sh[t] += u;
        __syncthreads();
    }
    const int agg = sh[255];
    if (t == 0) {
        if (b == 0) {
            g_blkpre[0] = agg;
            __threadfence();
            g_blkst[0] = 2;
            s_base = 0;
        } else {
            g_blkagg[b] = agg;
            __threadfence();
            g_blkst[b] = 1;
        }
    }
    if (b > 0 && t < 32) {        // warp-parallel lookback (warp 0)
        const int lane = t;
        int run = 0;
        int j = b - 1;
        while (true) {
            int idx = j - lane;
            int st;
            do { st = (idx >= 0) ? g_blkst[idx] : 2; }
            while (__any_sync(0xFFFFFFFFu, st == 0));
            unsigned m = __ballot_sync(0xFFFFFFFFu, st == 2);
            int L = (m == 0) ? 32 : (__ffs(m) - 1);
            int val = 0;
            if (idx >= 0 && lane <= L) {
                val = (lane == L) ? g_blkpre[idx] : g_blkagg[idx];
            }
#pragma unroll
            for (int o = 16; o > 0; o >>= 1) val += __shfl_xor_sync(0xFFFFFFFFu, val, o);
            run += val;
            if (m) break;
            j -= 32;
        }
        if (lane == 0) {
            g_blkpre[b] = run + agg;
            __threadfence();
            g_blkst[b] = 2;
            s_base = run;
        }
    }
    __syncthreads();
    const int base = s_base;
    if (i < n) {
        int excl = base + sh[t] - c;
        g_off[i] = excl;
        g_cur[i] = excl;
        g_inv[i] = 1.0f / (float)max(c, 1);
        if (i == n - 1) g_off[n] = base + sh[t];
    }
}

__device__ __forceinline__ void mma16816(float* c, const uint4& a, uint32_t b0, uint32_t b1) {
    asm volatile(
        "mma.sync.aligned.m16n8k16.row.col.f32.bf16.bf16.f32 "
        "{%0,%1,%2,%3}, {%4,%5,%6,%7}, {%8,%9}, {%0,%1,%2,%3};"
        : "+f"(c[0]), "+f"(c[1]), "+f"(c[2]), "+f"(c[3])
        : "r"(a.x), "r"(a.y), "r"(a.z), "r"(a.w), "r"(b0), "r"(b1));
}

// One 2048-edge CSR fill tile (work-stealing). Returns false when exhausted.
__device__ __forceinline__ bool fill_tile(const int* __restrict__ src,
                                          const int* __restrict__ dst, int E,
                                          int tid, int* s_tile) {
    const int ntile = (E + 2047) / 2048;
    if (tid == 0) *s_tile = atomicAdd(&g_work, 1);
    __syncthreads();
    const int tile = *s_tile;
    __syncthreads();
    if (tile >= ntile) return false;
    int e = tile * 2048 + tid * 4;
    if (e + 3 < E) {
        int4 d = *(const int4*)(dst + e);
        int4 s = *(const int4*)(src + e);
        g_csr[atomicAdd(&g_cur[d.x], 1)] = s.x;
        g_csr[atomicAdd(&g_cur[d.y], 1)] = s.y;
        g_csr[atomicAdd(&g_cur[d.z], 1)] = s.z;
        g_csr[atomicAdd(&g_cur[d.w], 1)] = s.w;
    } else {
        for (; e < E; e++) g_csr[atomicAdd(&g_cur[dst[e]], 1)] = src[e];
    }
    return true;
}

// Column-split persistent GEMM (OUT=128, NT=32): each CTA owns HALF the columns
// (16 nt tiles, 64 KB smem) -> 2 CTAs/SM, 32 warps. Warp = 1 mt-tile x 4 nt.
// cid=0 half produces p (fp16), cid=1 half produces q (fp32).
template<bool FILL>
__global__ __launch_bounds__(512, 2)
void k_mma32s(const uint32_t* __restrict__ Bh, const uint32_t* __restrict__ Bl,
              unsigned char* __restrict__ pq, int ngrp4, int nmt, int N,
              const int* __restrict__ src, const int* __restrict__ dst, int E) {
    constexpr int NTC = 16;                        // col tiles per CTA
    constexpr int BW2 = 8 * NTC * 64;              // u32 per half image
    constexpr int ROWB = 768;
    __shared__ uint32_t bsh[BW2];
    __shared__ uint32_t bsl[BW2];
    __shared__ int s_tile;

    const int tid = threadIdx.x;
    const int cid = blockIdx.x & 1;                // column half

    {   // stage half B image: per ks, nt range [cid*16, cid*16+16)
        const uint4* gh = (const uint4*)Bh;
        const uint4* gl = (const uint4*)Bl;
        uint4* s0 = (uint4*)bsh;
        uint4* s1 = (uint4*)bsl;
#pragma unroll
        for (int i = tid; i < BW2 / 4; i += 512) {
            int ks = i >> 8;                       // 256 uint4 per ks-half
            int r = i & 255;
            int gidx = ks * 512 + cid * 256 + r;
            s0[i] = gh[gidx];
            s1[i] = gl[gidx];
        }
    }
    __syncthreads();

    const int wid = tid >> 5, lane = tid & 31;
    const int wrow = wid & 3;                      // 1 mt-tile each (4 per group)
    const int ntb = (wid >> 2) * 4;                // 4 nt tiles per warp
    const uint2* sh2 = ((const uint2*)bsh) + lane;
    const uint2* sl2 = ((const uint2*)bsl) + lane;
    const int g = lane >> 2, t = lane & 3;
    const int step = gridDim.x >> 1;
    bool more_fill = FILL;

    for (int grp = blockIdx.x >> 1; grp < ngrp4; grp += step) {
        const int mt = grp * 4 + wrow;
        if (mt < nmt) {
            float acc[4][4];
#pragma unroll
            for (int nt = 0; nt < 4; nt++)
#pragma unroll
                for (int i = 0; i < 4; i++) acc[nt][i] = 0.f;

            const uint4* pah = ((const uint4*)g_ah) + (size_t)mt * 8 * 32 + lane;
            const uint4* pal = ((const uint4*)g_al) + (size_t)mt * 8 * 32 + lane;

#pragma unroll 1
            for (int ks = 0; ks < 8; ks++) {
                uint4 ah = pah[ks * 32];
                uint4 al = pal[ks * 32];
#pragma unroll
                for (int nt = 0; nt < 4; nt++) {
                    int i2 = (ks * NTC + ntb + nt) * 32;
                    uint2 wh = sh2[i2];
                    uint2 wlo = sl2[i2];
                    mma16816(acc[nt], ah, wh.x, wh.y);
                    mma16816(acc[nt], ah, wlo.x, wlo.y);
                    mma16816(acc[nt], al, wh.x, wh.y);
                }
            }

            const int r0 = mt * 16 + g, r1 = r0 + 8;
            const bool ok0 = r0 < N, ok1 = r1 < N;
#pragma unroll
            for (int nt = 0; nt < 4; nt++) {
                int col = (cid * NTC + ntb + nt) * 8 + 2 * t;
                if (col < 128) {    // p: fp16
                    if (ok0) *(__half2*)(pq + (size_t)r0 * ROWB + col * 2)
                                 = __floats2half2_rn(acc[nt][0], acc[nt][1]);
                    if (ok1) *(__half2*)(pq + (size_t)r1 * ROWB + col * 2)
                                 = __floats2half2_rn(acc[nt][2], acc[nt][3]);
                } else {            // q: fp32
                    int qc = col - 128;
                    if (ok0) *(float2*)(pq + (size_t)r0 * ROWB + 256 + qc * 4)
                                 = make_float2(acc[nt][0], acc[nt][1]);
                    if (ok1) *(float2*)(pq + (size_t)r1 * ROWB + 256 + qc * 4)
                                 = make_float2(acc[nt][2], acc[nt][3]);
                }
            }
        }
    }

    if (FILL) {                    // tail: work-stealing CSR fill
        while (more_fill) more_fill = fill_tile(src, dst, E, tid, &s_tile);
    }
}

// Persistent GEMM (layer 2, OUT=64): unchanged full-column kernel, 64 KB smem.
template<int NT>
__global__ __launch_bounds__(512)
void k_mma(const uint32_t* __restrict__ Bh, const uint32_t* __restrict__ Bl,
           unsigned char* __restrict__ pq, int ngrp, int nmt, int N) {
    constexpr int BW = 8 * NT * 64;
    constexpr int NTQ = NT / 4;
    constexpr int OUT = NT * 4;
    constexpr int ROWB = OUT * 6;
    extern __shared__ uint32_t bs[];
    uint32_t* bsh = bs;
    uint32_t* bsl = bs + BW;

    const int tid = threadIdx.x;
    {
        const uint4* gh = (const uint4*)Bh;
        const uint4* gl = (const uint4*)Bl;
        uint4* s0 = (uint4*)bsh;
        uint4* s1 = (uint4*)bsl;
#pragma unroll
        for (int i = tid; i < BW / 4; i += 512) { s0[i] = gh[i]; s1[i] = gl[i]; }
    }
    __syncthreads();

    const int wid = tid >> 5, lane = tid & 31;
    const int wrow = wid & 3;
    const int ntb = (wid >> 2) * NTQ;
    const uint2* sh2 = ((const uint2*)bsh) + lane;
    const uint2* sl2 = ((const uint2*)bsl) + lane;
    const int g = lane >> 2, t = lane & 3;
    const uint4 z4 = make_uint4(0, 0, 0, 0);

    for (int grp = blockIdx.x; grp < ngrp; grp += gridDim.x) {
        const int mt0 = grp * 8 + wrow * 2;
        const int mt1 = mt0 + 1;
        const bool v0 = mt0 < nmt, v1 = mt1 < nmt;
        if (!v0) continue;

        float acc[2][NTQ][4];
#pragma unroll
        for (int m = 0; m < 2; m++)
#pragma unroll
            for (int nt = 0; nt < NTQ; nt++)
#pragma unroll
                for (int i = 0; i < 4; i++) acc[m][nt][i] = 0.f;

        const uint4* pah0 = ((const uint4*)g_ah) + (size_t)mt0 * 8 * 32 + lane;
        const uint4* pal0 = ((const uint4*)g_al) + (size_t)mt0 * 8 * 32 + lane;
        const uint4* pah1 = ((const uint4*)g_ah) + (size_t)mt1 * 8 * 32 + lane;
        const uint4* pal1 = ((const uint4*)g_al) + (size_t)mt1 * 8 * 32 + lane;

#pragma unroll 1
        for (int ks = 0; ks < 8; ks++) {
            uint4 ah0 = pah0[ks * 32];
            uint4 al0 = pal0[ks * 32];
            uint4 ah1 = v1 ? pah1[ks * 32] : z4;
            uint4 al1 = v1 ? pal1[ks * 32] : z4;
#pragma unroll
            for (int nt = 0; nt < NTQ; nt++) {
                int i2 = (ks * NT + ntb + nt) * 32;
                uint2 wh = sh2[i2];
                uint2 wlo = sl2[i2];
                mma16816(acc[0][nt], ah0, wh.x, wh.y);
                mma16816(acc[0][nt], ah0, wlo.x, wlo.y);
                mma16816(acc[0][nt], al0, wh.x, wh.y);
                mma16816(acc[1][nt], ah1, wh.x, wh.y);
                mma16816(acc[1][nt], ah1, wlo.x, wlo.y);
                mma16816(acc[1][nt], al1, wh.x, wh.y);
            }
        }

#pragma unroll
        for (int m = 0; m < 2; m++) {
            const int mt = m ? mt1 : mt0;
            if (m && !v1) break;
            const int r0 = mt * 16 + g, r1 = r0 + 8;
            const bool ok0 = r0 < N, ok1 = r1 < N;
#pragma unroll
            for (int nt = 0; nt < NTQ; nt++) {
                int col = (ntb + nt) * 8 + 2 * t;
                if (col < OUT) {
                    if (ok0) *(__half2*)(pq + (size_t)r0 * ROWB + col * 2)
                                 = __floats2half2_rn(acc[m][nt][0], acc[m][nt][1]);
                    if (ok1) *(__half2*)(pq + (size_t)r1 * ROWB + col * 2)
                                 = __floats2half2_rn(acc[m][nt][2], acc[m][nt][3]);
                } else {
                    int qc = col - OUT;
                    if (ok0) *(float2*)(pq + (size_t)r0 * ROWB + OUT * 2 + qc * 4)
                                 = make_float2(acc[m][nt][0], acc[m][nt][1]);
                    if (ok1) *(float2*)(pq + (size_t)r1 * ROWB + OUT * 2 + qc * 4)
                                 = make_float2(acc[m][nt][2], acc[m][nt][3]);
                }
            }
        }
    }
}

// Fused: y = inv*agg(p_fp16) + q + b (+relu/dropout) -> next-layer frag image or out.
template<int OUT, bool DROP, bool FRAGS>
__global__ __launch_bounds__(512)
void k_gatherep(const unsigned char* __restrict__ pq, const float* __restrict__ u,
                const float* __restrict__ bias, float* __restrict__ outp, int N) {
    __shared__ float yt[16][132];
    constexpr int ROWB = OUT * 6;
    const int mt = blockIdx.x;
    const int tid = threadIdx.x;
    const int wid = tid >> 5, lane = tid & 31;
    const int r = mt * 16 + wid;
    const bool ok = r < N;

    if (OUT == 128) {
        float4 y = make_float4(0.f, 0.f, 0.f, 0.f);
        if (ok) {
            float4 sA = make_float4(0.f, 0.f, 0.f, 0.f);
            float4 sB = make_float4(0.f, 0.f, 0.f, 0.f);
            int j = g_off[r], j1 = g_off[r + 1];
            for (; j + 3 < j1; j += 4) {
                int s0 = g_csr[j], s1 = g_csr[j + 1], s2 = g_csr[j + 2], s3 = g_csr[j + 3];
                uint2 a = *((const uint2*)(pq + (size_t)s0 * ROWB) + lane);
                uint2 b = *((const uint2*)(pq + (size_t)s1 * ROWB) + lane);
                uint2 c = *((const uint2*)(pq + (size_t)s2 * ROWB) + lane);
                uint2 d = *((const uint2*)(pq + (size_t)s3 * ROWB) + lane);
                float2 a0 = __half22float2(*(__half2*)&a.x), a1 = __half22float2(*(__half2*)&a.y);
                float2 b0 = __half22float2(*(__half2*)&b.x), b1 = __half22float2(*(__half2*)&b.y);
                float2 c0 = __half22float2(*(__half2*)&c.x), c1 = __half22float2(*(__half2*)&c.y);
                float2 d0 = __half22float2(*(__half2*)&d.x), d1 = __half22float2(*(__half2*)&d.y);
                sA.x += a0.x + c0.x; sA.y += a0.y + c0.y; sA.z += a1.x + c1.x; sA.w += a1.y + c1.y;
                sB.x += b0.x + d0.x; sB.y += b0.y + d0.y; sB.z += b1.x + d1.x; sB.w += b1.y + d1.y;
            }
            for (; j < j1; j++) {
                int s0 = g_csr[j];
                uint2 a = *((const uint2*)(pq + (size_t)s0 * ROWB) + lane);
                float2 a0 = __half22float2(*(__half2*)&a.x), a1 = __half22float2(*(__half2*)&a.y);
                sA.x += a0.x; sA.y += a0.y; sA.z += a1.x; sA.w += a1.y;
            }
            float iv = g_inv[r];
            float4 q = ((const float4*)(pq + (size_t)r * ROWB + OUT * 2))[lane];
            float4 b = ((const float4*)bias)[lane];
            y.x = iv * (sA.x + sB.x) + q.x + b.x;
            y.y = iv * (sA.y + sB.y) + q.y + b.y;
            y.z = iv * (sA.z + sB.z) + q.z + b.z;
            y.w = iv * (sA.w + sB.w) + q.w + b.w;
            if (DROP) {
                const float kinv = 1.0f / 0.7f;
                float4 uu = ((const float4*)u)[(size_t)r * 32 + lane];
                y.x = (y.x > 0.f ? y.x : 0.f) * (uu.x >= 0.3f ? kinv : 0.f);
                y.y = (y.y > 0.f ? y.y : 0.f) * (uu.y >= 0.3f ? kinv : 0.f);
                y.z = (y.z > 0.f ? y.z : 0.f) * (uu.z >= 0.3f ? kinv : 0.f);
                y.w = (y.w > 0.f ? y.w : 0.f) * (uu.w >= 0.3f ? kinv : 0.f);
            }
        }
        if (FRAGS) {
            yt[wid][lane * 4 + 0] = y.x;
            yt[wid][lane * 4 + 1] = y.y;
            yt[wid][lane * 4 + 2] = y.z;
            yt[wid][lane * 4 + 3] = y.w;
        } else if (ok) {
            ((float4*)outp)[(size_t)r * 32 + lane] = y;
        }
    } else {  // OUT == 64
        if (ok) {
            float2 sA = make_float2(0.f, 0.f), sB = make_float2(0.f, 0.f);
            int j = g_off[r], j1 = g_off[r + 1];
            for (; j + 3 < j1; j += 4) {
                int s0 = g_csr[j], s1 = g_csr[j + 1], s2 = g_csr[j + 2], s3 = g_csr[j + 3];
                float2 a = __half22float2(*((const __half2*)(pq + (size_t)s0 * ROWB) + lane));
                float2 b = __half22float2(*((const __half2*)(pq + (size_t)s1 * ROWB) + lane));
                float2 c = __half22float2(*((const __half2*)(pq + (size_t)s2 * ROWB) + lane));
                float2 d = __half22float2(*((const __half2*)(pq + (size_t)s3 * ROWB) + lane));
                sA.x += a.x + c.x; sA.y += a.y + c.y;
                sB.x += b.x + d.x; sB.y += b.y + d.y;
            }
            for (; j < j1; j++) {
                float2 a = __half22float2(*((const __half2*)(pq + (size_t)g_csr[j] * ROWB) + lane));
                sA.x += a.x; sA.y += a.y;
            }
            float iv = g_inv[r];
            float2 q = ((const float2*)(pq + (size_t)r * ROWB + OUT * 2))[lane];
            float2 b = ((const float2*)bias)[lane];
            float2 y;
            y.x = iv * (sA.x + sB.x) + q.x + b.x;
            y.y = iv * (sA.y + sB.y) + q.y + b.y;
            ((float2*)outp)[(size_t)r * 32 + lane] = y;
        }
    }

    if (FRAGS) {
        __syncthreads();
        const int base = mt * 1024;
#pragma unroll
        for (int i = tid; i < 1024; i += 512) {
            int ks = i >> 7, l = (i >> 2) & 31, reg = i & 3;
            int gg = (l >> 2) + 8 * (reg & 1);
            int c = 2 * (l & 3) + 16 * ks + 8 * (reg >> 1);
            uint32_t h, lo2;
            split2(yt[gg][c], yt[gg][c + 1], h, lo2);
            g_ah[base + i] = h;
            g_al[base + i] = lo2;
        }
    }
}

extern "C" void kernel_launch(void* const* d_in, const int* in_sizes, int n_in,
                              void* d_out, int out_size) {
    const float* x   = (const float*)d_in[0];
    const float* u1  = (const float*)d_in[1];
    const float* u2  = (const float*)d_in[2];
    const float* wl0 = (const float*)d_in[3];
    const float* bl0 = (const float*)d_in[4];
    const float* wr0 = (const float*)d_in[5];
    const float* wl1 = (const float*)d_in[6];
    const float* bl1 = (const float*)d_in[7];
    const float* wr1 = (const float*)d_in[8];
    const float* wl2 = (const float*)d_in[9];
    const float* bl2 = (const float*)d_in[10];
    const float* wr2 = (const float*)d_in[11];
    const int*   ei  = (const int*)d_in[12];

    const int N = in_sizes[0] / 128;
    const int E = in_sizes[12] / 2;
    const int* src = ei;
    const int* dst = ei + E;
    float* out = (float*)d_out;

    unsigned char* pq;
    uint32_t *bh, *bl;
    cudaGetSymbolAddress((void**)&pq, g_pq);
    cudaGetSymbolAddress((void**)&bh, g_bh);
    cudaGetSymbolAddress((void**)&bl, g_bl);
    const int LS = 8 * 32 * 32 * 2;

    int sms = 148;
    cudaDeviceGetAttribute(&sms, cudaDevAttrMultiProcessorCount, 0);

    const int smem16 = 2 * 8 * 16 * 64 * 4;   // 64 KB (layer-2 kernel)
    cudaFuncSetAttribute(k_mma<16>, cudaFuncAttributeMaxDynamicSharedMemorySize, smem16);

    const int tb = 256;
    const int nmt = (N + 15) / 16;
    const int ngrp4 = (nmt + 3) / 4;          // split kernel groups (4 mt each)
    const int ngrp = (nmt + 7) / 8;           // layer-2 groups
    const int nsb = (N + 255) / 256;
    const int gms = 2 * sms;                  // split kernel grid (2 col halves)
    const int gm16 = (2 * sms < ngrp) ? 2 * sms : ngrp;
    const int prepB = (nmt * 8 * 32 + tb - 1) / tb;
    const int cntB = (E / 4 + tb) / tb + 1;

    // 1: setup (zero cnt/flags + weight images)
    k_setup<<<(N + tb - 1) / tb, tb>>>(wl0, wr0, wl1, wr1, wl2, wr2, N);
    // 2: layer-0 A frags + edge count (fused, disjoint block ranges)
    k_prep_count<<<prepB + cntB, tb>>>(x, dst, prepB, nmt, N, E);
    // 3: CSR offsets (single-kernel decoupled-lookback scan)
    k_scanlb<<<nsb, 256>>>(N);
    // 4: layer-0 GEMM (column-split, 2 CTAs/SM) + CSR fill tail
    k_mma32s<true><<<gms, 512>>>(bh + 0 * LS, bl + 0 * LS, pq, ngrp4, nmt, N, src, dst, E);
    // 5: layer-0 aggregate + epilogue -> h1 frags
    k_gatherep<128, true, true><<<nmt, 512>>>(pq, u1, bl0, nullptr, N);
    // 6-7: layer 1
    k_mma32s<false><<<gms, 512>>>(bh + 1 * LS, bl + 1 * LS, pq, ngrp4, nmt, N, src, dst, E);
    k_gatherep<128, true, true><<<nmt, 512>>>(pq, u2, bl1, nullptr, N);
    // 8-9: layer 2
    k_mma<16><<<gm16, 512, smem16>>>(bh + 2 * LS, bl + 2 * LS, pq, ngrp, nmt, N);
    k_gatherep<64, false, false><<<nmt, 512>>>(pq, nullptr, bl2, out, N);
}